// round 2
// baseline (speedup 1.0000x reference)
#include <cuda_runtime.h>
#include <math.h>

#define NTOK 4096
#define DDIM 512
#define QKV  768
#define KSEL 819

// ---------------- scratch (device globals; no runtime allocation) -------------
__device__ float g_lqkv[NTOK * QKV];
__device__ float g_cqkv[NTOK * QKV];
__device__ float g_h[NTOK * 256];
__device__ float g_scores[NTOK];
__device__ int   g_mask[NTOK];
__device__ float g_invl[8 * NTOK];                 // reciprocal softmax denominators
__device__ float g_S[(size_t)8 * NTOK * NTOK];     // logits -> exp numerators, 536MB
__device__ float g_o[2 * NTOK * 256];              // per-branch attention outputs

// ---------------- generic tiled fp32 GEMM: C = A@W + bias (opt gelu/accum) ----
__global__ __launch_bounds__(256) void gemm_kernel(
    const float* __restrict__ A, const float* __restrict__ W,
    const float* __restrict__ bias, float* __restrict__ C,
    int M, int Nc, int K, int gelu_flag, int accum)
{
    __shared__ float As[64][68];   // [k][m] transposed A tile
    __shared__ float Ws[64][68];   // [k][n] natural W tile
    int tx = threadIdx.x & 15, ty = threadIdx.x >> 4;
    int n0 = blockIdx.x * 64, m0 = blockIdx.y * 64;
    float acc[4][4];
#pragma unroll
    for (int i = 0; i < 4; i++)
#pragma unroll
        for (int j = 0; j < 4; j++) acc[i][j] = 0.f;

    for (int k0 = 0; k0 < K; k0 += 64) {
        for (int t = threadIdx.x; t < 4096; t += 256) {
            int m = t >> 6, k = t & 63;
            As[k][m] = A[(size_t)(m0 + m) * K + k0 + k];
        }
        for (int t = threadIdx.x; t < 4096; t += 256) {
            int k = t >> 6, n = t & 63;
            Ws[k][n] = W[(size_t)(k0 + k) * Nc + n0 + n];
        }
        __syncthreads();
#pragma unroll 16
        for (int kk = 0; kk < 64; kk++) {
            float4 a4 = *(const float4*)&As[kk][ty * 4];
            float4 b4 = *(const float4*)&Ws[kk][tx * 4];
            float a[4] = {a4.x, a4.y, a4.z, a4.w};
            float b[4] = {b4.x, b4.y, b4.z, b4.w};
#pragma unroll
            for (int i = 0; i < 4; i++)
#pragma unroll
                for (int j = 0; j < 4; j++) acc[i][j] += a[i] * b[j];
        }
        __syncthreads();
    }
#pragma unroll
    for (int i = 0; i < 4; i++) {
        int m = m0 + ty * 4 + i;
        float* crow = C + (size_t)m * Nc + n0 + tx * 4;
        float v[4];
#pragma unroll
        for (int j = 0; j < 4; j++) {
            float c = acc[i][j] + bias[n0 + tx * 4 + j];
            if (gelu_flag)
                c = 0.5f * c * (1.0f + erff(c * 0.70710678118654752f));
            v[j] = c;
        }
        if (accum) {
            float4 prev = *(const float4*)crow;
            v[0] += prev.x; v[1] += prev.y; v[2] += prev.z; v[3] += prev.w;
        }
        float4 o = make_float4(v[0], v[1], v[2], v[3]);
        *(float4*)crow = o;
    }
}

// ---------------- saliency scores: scores[t] = h[t,:] . W_s2 + b_s2 ----------
__global__ __launch_bounds__(256) void scores_kernel(
    const float* __restrict__ Ws2, const float* __restrict__ bs2)
{
    int t = blockIdx.x * 8 + (threadIdx.x >> 5);
    int lane = threadIdx.x & 31;
    const float* hp = g_h + (size_t)t * 256;
    float s = 0.f;
    for (int i = lane; i < 256; i += 32) s += hp[i] * Ws2[i];
#pragma unroll
    for (int off = 16; off; off >>= 1) s += __shfl_xor_sync(0xffffffffu, s, off);
    if (lane == 0) g_scores[t] = s + bs2[0];
}

// ---------------- top-k mask via exact rank (tie-break = smaller index) ------
__global__ __launch_bounds__(256) void mask_kernel()
{
    __shared__ float sc[NTOK];
    for (int i = threadIdx.x; i < NTOK; i += 256) sc[i] = g_scores[i];
    __syncthreads();
    int i = blockIdx.x * 256 + threadIdx.x;
    float si = sc[i];
    int cnt = 0;
    for (int j = 0; j < NTOK; j++) {
        float sj = sc[j];
        cnt += (sj > si) || (sj == si && j < i);
    }
    g_mask[i] = (cnt < KSEL) ? 1 : 0;
}

// ---------------- logits: S[hb][q][k] = 0.125 * q.k ---------------------------
__global__ __launch_bounds__(256) void qk_kernel()
{
    int hb = blockIdx.z;
    const float* buf = (hb < 4) ? g_lqkv : g_cqkv;
    int h = hb & 3;
    int q0 = blockIdx.y * 64, k0 = blockIdx.x * 64;
    __shared__ float Qs[64][68];   // [d][q]
    __shared__ float Ks[64][68];   // [d][k]
    int tx = threadIdx.x & 15, ty = threadIdx.x >> 4;

    for (int t = threadIdx.x; t < 4096; t += 256) {
        int r = t >> 6, d = t & 63;
        Qs[d][r] = buf[(size_t)(q0 + r) * QKV + h * 64 + d];
        Ks[d][r] = buf[(size_t)(k0 + r) * QKV + 256 + h * 64 + d];
    }
    __syncthreads();
    float acc[4][4];
#pragma unroll
    for (int i = 0; i < 4; i++)
#pragma unroll
        for (int j = 0; j < 4; j++) acc[i][j] = 0.f;
#pragma unroll 16
    for (int dd = 0; dd < 64; dd++) {
        float4 a4 = *(const float4*)&Qs[dd][ty * 4];
        float4 b4 = *(const float4*)&Ks[dd][tx * 4];
        float a[4] = {a4.x, a4.y, a4.z, a4.w};
        float b[4] = {b4.x, b4.y, b4.z, b4.w};
#pragma unroll
        for (int i = 0; i < 4; i++)
#pragma unroll
            for (int j = 0; j < 4; j++) acc[i][j] += a[i] * b[j];
    }
#pragma unroll
    for (int i = 0; i < 4; i++) {
        float* sp = g_S + ((size_t)hb * NTOK + q0 + ty * 4 + i) * NTOK + k0 + tx * 4;
        float4 o = make_float4(acc[i][0] * 0.125f, acc[i][1] * 0.125f,
                               acc[i][2] * 0.125f, acc[i][3] * 0.125f);
        *(float4*)sp = o;
    }
}

// ---------------- row softmax in place: S <- exp(S-m) (masked), invl stored --
__global__ __launch_bounds__(256) void softmax_kernel()
{
    int q = blockIdx.x, hb = blockIdx.y;
    float* Sp = g_S + ((size_t)hb * NTOK + q) * NTOK;
    bool content = hb >= 4;
    int tid = threadIdx.x;
    __shared__ float red[8];

    float mx = -1e30f;
    for (int k = tid; k < NTOK; k += 256) {
        float s = Sp[k];
        if (!content || g_mask[k]) mx = fmaxf(mx, s);
    }
#pragma unroll
    for (int off = 16; off; off >>= 1) mx = fmaxf(mx, __shfl_xor_sync(0xffffffffu, mx, off));
    if ((tid & 31) == 0) red[tid >> 5] = mx;
    __syncthreads();
    if (tid == 0) {
        float m = red[0];
#pragma unroll
        for (int i = 1; i < 8; i++) m = fmaxf(m, red[i]);
        red[0] = m;
    }
    __syncthreads();
    float m = red[0];
    __syncthreads();

    float sum = 0.f;
    for (int k = tid; k < NTOK; k += 256) {
        float s = Sp[k];
        float e = 0.f;
        if (!content || g_mask[k]) e = __expf(s - m);
        Sp[k] = e;
        sum += e;
    }
#pragma unroll
    for (int off = 16; off; off >>= 1) sum += __shfl_xor_sync(0xffffffffu, sum, off);
    if ((tid & 31) == 0) red[tid >> 5] = sum;
    __syncthreads();
    if (tid == 0) {
        float t = 0.f;
#pragma unroll
        for (int i = 0; i < 8; i++) t += red[i];
        g_invl[hb * NTOK + q] = 1.0f / t;
    }
}

// ---------------- head-mean of attention probabilities -> attn output --------
__global__ __launch_bounds__(256) void mean_kernel(float* __restrict__ attn_out)
{
    int b = blockIdx.z, q = blockIdx.y;
    int k = (blockIdx.x * 256 + threadIdx.x) * 4;
    float4 acc = make_float4(0.f, 0.f, 0.f, 0.f);
#pragma unroll
    for (int h = 0; h < 4; h++) {
        int hb = b * 4 + h;
        float inv = g_invl[hb * NTOK + q];
        float4 e = *(const float4*)&g_S[((size_t)hb * NTOK + q) * NTOK + k];
        acc.x += e.x * inv; acc.y += e.y * inv;
        acc.z += e.z * inv; acc.w += e.w * inv;
    }
    acc.x *= 0.25f; acc.y *= 0.25f; acc.z *= 0.25f; acc.w *= 0.25f;
    *(float4*)&attn_out[((size_t)(b * NTOK + q)) * NTOK + k] = acc;
}

// ---------------- PV: o[hb][q][d] = invl[q] * sum_k e[q][k] * v[k][d] --------
__global__ __launch_bounds__(256) void pv_kernel()
{
    int hb = blockIdx.z;
    const float* buf = (hb < 4) ? g_lqkv : g_cqkv;
    int h = hb & 3, b = hb >> 2;
    int q0 = blockIdx.y * 64;
    __shared__ float Es[64][68];  // [k][q]
    __shared__ float Vs[64][68];  // [k][d]
    int tx = threadIdx.x & 15, ty = threadIdx.x >> 4;

    float acc[4][4];
#pragma unroll
    for (int i = 0; i < 4; i++)
#pragma unroll
        for (int j = 0; j < 4; j++) acc[i][j] = 0.f;

    for (int k0 = 0; k0 < NTOK; k0 += 64) {
        for (int t = threadIdx.x; t < 4096; t += 256) {
            int r = t >> 6, c = t & 63;
            Es[c][r] = g_S[((size_t)hb * NTOK + q0 + r) * NTOK + k0 + c];
            Vs[r][c] = buf[(size_t)(k0 + r) * QKV + 512 + h * 64 + c];
        }
        __syncthreads();
#pragma unroll 16
        for (int kk = 0; kk < 64; kk++) {
            float4 a4 = *(const float4*)&Es[kk][ty * 4];
            float4 b4 = *(const float4*)&Vs[kk][tx * 4];
            float a[4] = {a4.x, a4.y, a4.z, a4.w};
            float bb[4] = {b4.x, b4.y, b4.z, b4.w};
#pragma unroll
            for (int i = 0; i < 4; i++)
#pragma unroll
                for (int j = 0; j < 4; j++) acc[i][j] += a[i] * bb[j];
        }
        __syncthreads();
    }
#pragma unroll
    for (int i = 0; i < 4; i++) {
        float inv = g_invl[hb * NTOK + q0 + ty * 4 + i];
        float* op = g_o + (size_t)b * NTOK * 256 + (size_t)(q0 + ty * 4 + i) * 256
                    + h * 64 + tx * 4;
        float4 o = make_float4(acc[i][0] * inv, acc[i][1] * inv,
                               acc[i][2] * inv, acc[i][3] * inv);
        *(float4*)op = o;
    }
}

// -----------------------------------------------------------------------------
extern "C" void kernel_launch(void* const* d_in, const int* in_sizes, int n_in,
                              void* d_out, int out_size)
{
    const float* x       = (const float*)d_in[0];
    const float* W_lqkv  = (const float*)d_in[1];
    const float* b_lqkv  = (const float*)d_in[2];
    const float* W_cqkv  = (const float*)d_in[3];
    const float* b_cqkv  = (const float*)d_in[4];
    const float* W_lproj = (const float*)d_in[5];
    const float* b_lproj = (const float*)d_in[6];
    const float* W_cproj = (const float*)d_in[7];
    const float* b_cproj = (const float*)d_in[8];
    const float* W_s1    = (const float*)d_in[9];
    const float* b_s1    = (const float*)d_in[10];
    const float* W_s2    = (const float*)d_in[11];
    const float* b_s2    = (const float*)d_in[12];

    float* out  = (float*)d_out;
    float* attn = out + (size_t)NTOK * DDIM;

    float *p_lqkv, *p_cqkv, *p_h, *p_o;
    cudaGetSymbolAddress((void**)&p_lqkv, g_lqkv);
    cudaGetSymbolAddress((void**)&p_cqkv, g_cqkv);
    cudaGetSymbolAddress((void**)&p_h,    g_h);
    cudaGetSymbolAddress((void**)&p_o,    g_o);

    dim3 b256(256);

    // QKV + saliency projections
    gemm_kernel<<<dim3(12, 64), b256>>>(x, W_lqkv, b_lqkv, p_lqkv, NTOK, 768, DDIM, 0, 0);
    gemm_kernel<<<dim3(12, 64), b256>>>(x, W_cqkv, b_cqkv, p_cqkv, NTOK, 768, DDIM, 0, 0);
    gemm_kernel<<<dim3(4, 64),  b256>>>(x, W_s1,   b_s1,   p_h,    NTOK, 256, DDIM, 1, 0);

    scores_kernel<<<512, b256>>>(W_s2, b_s2);
    mask_kernel<<<16, b256>>>();

    qk_kernel<<<dim3(64, 64, 8), b256>>>();
    softmax_kernel<<<dim3(NTOK, 8), b256>>>();
    mean_kernel<<<dim3(4, NTOK, 2), b256>>>(attn);
    pv_kernel<<<dim3(1, 64, 8), b256>>>();

    // output projections: out = lo@W_lproj + b_lproj + co@W_cproj + b_cproj
    gemm_kernel<<<dim3(8, 64), b256>>>(p_o,               W_lproj, b_lproj, out, NTOK, DDIM, 256, 0, 0);
    gemm_kernel<<<dim3(8, 64), b256>>>(p_o + NTOK * 256,  W_cproj, b_cproj, out, NTOK, DDIM, 256, 0, 1);
}

// round 3
// speedup vs baseline: 1.8980x; 1.8980x over previous
#include <cuda_runtime.h>
#include <math.h>

#define NTOK 4096
#define DDIM 512
#define QKV  768
#define KSEL 819

// ---------------- scratch (device globals; no runtime allocation) -------------
__device__ float g_lqkv[NTOK * QKV];
__device__ float g_cqkv[NTOK * QKV];
__device__ float g_h[NTOK * 256];
__device__ float g_scores[NTOK];
__device__ int   g_mask[NTOK];
__device__ float g_invl[8 * NTOK];
__device__ float g_S[(size_t)8 * NTOK * NTOK];     // logits -> exp numerators
__device__ float g_o[2 * NTOK * 256];              // per-branch attention outputs

// ---------------- tf32 helpers ------------------------------------------------
__device__ __forceinline__ unsigned f2tf(float f) {
    unsigned r;
    asm("cvt.rna.tf32.f32 %0, %1;" : "=r"(r) : "f"(f));
    return r;
}
__device__ __forceinline__ void mma8(float& c0, float& c1, float& c2, float& c3,
                                     unsigned a0, unsigned a1, unsigned a2, unsigned a3,
                                     unsigned b0, unsigned b1)
{
    asm volatile(
        "mma.sync.aligned.m16n8k8.row.col.f32.tf32.tf32.f32 "
        "{%0,%1,%2,%3},{%4,%5,%6,%7},{%8,%9},{%0,%1,%2,%3};"
        : "+f"(c0), "+f"(c1), "+f"(c2), "+f"(c3)
        : "r"(a0), "r"(a1), "r"(a2), "r"(a3), "r"(b0), "r"(b1));
}

// ---------------- tf32 GEMM: C = A@W + bias  (A:[M,K] k-contig, W:[K,N]) ------
// block tile 128m x 64n, k-chunk 32; 4 warps, warp tile 32m x 64n
__global__ __launch_bounds__(128) void proj_tf32(
    const float* __restrict__ A, const float* __restrict__ W,
    const float* __restrict__ bias, float* __restrict__ C, int Nc, int K)
{
    __shared__ unsigned Xs[128][36];   // [m][k]  (36 = 4 mod 32 -> frag conflict-free)
    __shared__ unsigned Ws[32][72];    // [k][n]  (72 = 8 mod 32 -> frag conflict-free)
    int t = threadIdx.x & 3, g = (threadIdx.x >> 2) & 7, w = threadIdx.x >> 5;
    int m0 = blockIdx.y * 128, n0 = blockIdx.x * 64;

    float acc[2][8][4];
#pragma unroll
    for (int mi = 0; mi < 2; mi++)
#pragma unroll
        for (int ni = 0; ni < 8; ni++)
#pragma unroll
            for (int c = 0; c < 4; c++) acc[mi][ni][c] = 0.f;

    for (int k0 = 0; k0 < K; k0 += 32) {
#pragma unroll
        for (int it = 0; it < 8; it++) {
            int idx = it * 128 + threadIdx.x;
            int row = idx >> 3, c4 = (idx & 7) * 4;
            float4 v = *(const float4*)&A[(size_t)(m0 + row) * K + k0 + c4];
            Xs[row][c4 + 0] = f2tf(v.x); Xs[row][c4 + 1] = f2tf(v.y);
            Xs[row][c4 + 2] = f2tf(v.z); Xs[row][c4 + 3] = f2tf(v.w);
        }
#pragma unroll
        for (int it = 0; it < 4; it++) {
            int idx = it * 128 + threadIdx.x;
            int kr = idx >> 4, n4 = (idx & 15) * 4;
            float4 v = *(const float4*)&W[(size_t)(k0 + kr) * Nc + n0 + n4];
            Ws[kr][n4 + 0] = f2tf(v.x); Ws[kr][n4 + 1] = f2tf(v.y);
            Ws[kr][n4 + 2] = f2tf(v.z); Ws[kr][n4 + 3] = f2tf(v.w);
        }
        __syncthreads();
#pragma unroll
        for (int ks = 0; ks < 4; ks++) {
            int kl = ks * 8;
            unsigned a[2][4];
#pragma unroll
            for (int mi = 0; mi < 2; mi++) {
                int r = w * 32 + mi * 16 + g;
                a[mi][0] = Xs[r][kl + t];      a[mi][1] = Xs[r + 8][kl + t];
                a[mi][2] = Xs[r][kl + t + 4];  a[mi][3] = Xs[r + 8][kl + t + 4];
            }
#pragma unroll
            for (int ni = 0; ni < 8; ni++) {
                unsigned b0 = Ws[kl + t][ni * 8 + g];
                unsigned b1 = Ws[kl + t + 4][ni * 8 + g];
#pragma unroll
                for (int mi = 0; mi < 2; mi++)
                    mma8(acc[mi][ni][0], acc[mi][ni][1], acc[mi][ni][2], acc[mi][ni][3],
                         a[mi][0], a[mi][1], a[mi][2], a[mi][3], b0, b1);
            }
        }
        __syncthreads();
    }
#pragma unroll
    for (int mi = 0; mi < 2; mi++)
#pragma unroll
        for (int ni = 0; ni < 8; ni++) {
            int m = m0 + w * 32 + mi * 16 + g;
            int n = n0 + ni * 8 + 2 * t;
            float bv0 = bias[n], bv1 = bias[n + 1];
            float2 r0 = make_float2(acc[mi][ni][0] + bv0, acc[mi][ni][1] + bv1);
            float2 r1 = make_float2(acc[mi][ni][2] + bv0, acc[mi][ni][3] + bv1);
            *(float2*)&C[(size_t)m * Nc + n] = r0;
            *(float2*)&C[(size_t)(m + 8) * Nc + n] = r1;
        }
}

// ---------------- tf32 QK^T: S[hb][q][k] = 0.125 * q.k ------------------------
// block tile 128q x 128k, head-dim in 2 chunks of 32; 4 warps, warp tile 32q x 128k
__global__ __launch_bounds__(128) void qk_tf32()
{
    __shared__ unsigned Qs[128][36];   // [q][d]
    __shared__ unsigned Ks[128][36];   // [ktok][d]
    int hb = blockIdx.z;
    const float* buf = (hb < 4) ? g_lqkv : g_cqkv;
    int h = hb & 3;
    int q0 = blockIdx.y * 128, k0 = blockIdx.x * 128;
    int t = threadIdx.x & 3, g = (threadIdx.x >> 2) & 7, w = threadIdx.x >> 5;

    float acc[2][16][4];
#pragma unroll
    for (int mi = 0; mi < 2; mi++)
#pragma unroll
        for (int ni = 0; ni < 16; ni++)
#pragma unroll
            for (int c = 0; c < 4; c++) acc[mi][ni][c] = 0.f;

    for (int dc = 0; dc < 64; dc += 32) {
#pragma unroll
        for (int it = 0; it < 8; it++) {
            int idx = it * 128 + threadIdx.x;
            int row = idx >> 3, c4 = (idx & 7) * 4;
            float4 v = *(const float4*)&buf[(size_t)(q0 + row) * QKV + h * 64 + dc + c4];
            Qs[row][c4 + 0] = f2tf(v.x); Qs[row][c4 + 1] = f2tf(v.y);
            Qs[row][c4 + 2] = f2tf(v.z); Qs[row][c4 + 3] = f2tf(v.w);
            float4 u = *(const float4*)&buf[(size_t)(k0 + row) * QKV + 256 + h * 64 + dc + c4];
            Ks[row][c4 + 0] = f2tf(u.x); Ks[row][c4 + 1] = f2tf(u.y);
            Ks[row][c4 + 2] = f2tf(u.z); Ks[row][c4 + 3] = f2tf(u.w);
        }
        __syncthreads();
#pragma unroll
        for (int ks = 0; ks < 4; ks++) {
            int kl = ks * 8;
            unsigned a[2][4];
#pragma unroll
            for (int mi = 0; mi < 2; mi++) {
                int r = w * 32 + mi * 16 + g;
                a[mi][0] = Qs[r][kl + t];      a[mi][1] = Qs[r + 8][kl + t];
                a[mi][2] = Qs[r][kl + t + 4];  a[mi][3] = Qs[r + 8][kl + t + 4];
            }
#pragma unroll
            for (int ni = 0; ni < 16; ni++) {
                unsigned b0 = Ks[ni * 8 + g][kl + t];
                unsigned b1 = Ks[ni * 8 + g][kl + t + 4];
#pragma unroll
                for (int mi = 0; mi < 2; mi++)
                    mma8(acc[mi][ni][0], acc[mi][ni][1], acc[mi][ni][2], acc[mi][ni][3],
                         a[mi][0], a[mi][1], a[mi][2], a[mi][3], b0, b1);
            }
        }
        __syncthreads();
    }
#pragma unroll
    for (int mi = 0; mi < 2; mi++)
#pragma unroll
        for (int ni = 0; ni < 16; ni++) {
            int q = q0 + w * 32 + mi * 16 + g;
            int kk = k0 + ni * 8 + 2 * t;
            size_t r0 = ((size_t)hb * NTOK + q) * NTOK + kk;
            size_t r1 = ((size_t)hb * NTOK + q + 8) * NTOK + kk;
            *(float2*)&g_S[r0] = make_float2(acc[mi][ni][0] * 0.125f, acc[mi][ni][1] * 0.125f);
            *(float2*)&g_S[r1] = make_float2(acc[mi][ni][2] * 0.125f, acc[mi][ni][3] * 0.125f);
        }
}

// ---------------- fused softmax (4 planes) + head-mean -> attn ----------------
__global__ __launch_bounds__(256) void softmax_mean(float* __restrict__ attn)
{
    int q = blockIdx.x, b = blockIdx.y;
    int tid = threadIdx.x, lane = tid & 31, wid = tid >> 5;
    __shared__ int maskS[NTOK];
    __shared__ float red[4][8];
    __shared__ float bc[8];

    size_t ps = (size_t)NTOK * NTOK;
    float* Sp = g_S + ((size_t)(b * 4) * NTOK + q) * NTOK;

    if (b) {
        for (int k = tid; k < NTOK; k += 256) maskS[k] = g_mask[k];
    }
    __syncthreads();

    // pass 1: per-plane max
    float m[4] = {-1e30f, -1e30f, -1e30f, -1e30f};
    for (int k = tid; k < NTOK; k += 256) {
        if (!b || maskS[k]) {
#pragma unroll
            for (int hh = 0; hh < 4; hh++)
                m[hh] = fmaxf(m[hh], Sp[(size_t)hh * ps + k]);
        }
    }
#pragma unroll
    for (int hh = 0; hh < 4; hh++) {
        float v = m[hh];
#pragma unroll
        for (int off = 16; off; off >>= 1) v = fmaxf(v, __shfl_xor_sync(0xffffffffu, v, off));
        if (lane == 0) red[hh][wid] = v;
    }
    __syncthreads();
    if (tid == 0) {
#pragma unroll
        for (int hh = 0; hh < 4; hh++) {
            float v = red[hh][0];
#pragma unroll
            for (int i = 1; i < 8; i++) v = fmaxf(v, red[hh][i]);
            bc[hh] = v;
        }
    }
    __syncthreads();
    float mx[4] = {bc[0], bc[1], bc[2], bc[3]};
    __syncthreads();

    // pass 2: exp in-place + sums
    float s[4] = {0.f, 0.f, 0.f, 0.f};
    for (int k = tid; k < NTOK; k += 256) {
        bool on = (!b) || maskS[k];
#pragma unroll
        for (int hh = 0; hh < 4; hh++) {
            float e = 0.f;
            if (on) e = __expf(Sp[(size_t)hh * ps + k] - mx[hh]);
            Sp[(size_t)hh * ps + k] = e;
            s[hh] += e;
        }
    }
#pragma unroll
    for (int hh = 0; hh < 4; hh++) {
        float v = s[hh];
#pragma unroll
        for (int off = 16; off; off >>= 1) v += __shfl_xor_sync(0xffffffffu, v, off);
        if (lane == 0) red[hh][wid] = v;
    }
    __syncthreads();
    if (tid == 0) {
#pragma unroll
        for (int hh = 0; hh < 4; hh++) {
            float v = 0.f;
#pragma unroll
            for (int i = 0; i < 8; i++) v += red[hh][i];
            float inv = 1.0f / v;
            g_invl[(b * 4 + hh) * NTOK + q] = inv;
            bc[4 + hh] = inv;
        }
    }
    __syncthreads();
    float iv[4] = {bc[4], bc[5], bc[6], bc[7]};

    // pass 3: head mean -> attn (rows just written are L2-hot)
    float* arow = attn + ((size_t)(b * NTOK + q)) * NTOK;
    for (int k = tid; k < NTOK; k += 256) {
        float a = 0.f;
#pragma unroll
        for (int hh = 0; hh < 4; hh++) a += Sp[(size_t)hh * ps + k] * iv[hh];
        arow[k] = a * 0.25f;
    }
}

// ---------------- tf32 PV:  o^T[d][q] = sum_k V[k][d] * E[q][k]  --------------
// block tile M=64(d) x N=128(q), k-chunks of 32; 4 warps, warp tile 64d x 32q
__global__ __launch_bounds__(128) void pv_tf32()
{
    __shared__ unsigned Ss[128][36];   // [q][k]
    __shared__ unsigned Vs[32][72];    // [k][d]
    int hb = blockIdx.y;
    const float* buf = (hb < 4) ? g_lqkv : g_cqkv;
    int h = hb & 3, bB = hb >> 2;
    int q0 = blockIdx.x * 128;
    int t = threadIdx.x & 3, g = (threadIdx.x >> 2) & 7, w = threadIdx.x >> 5;

    float acc[4][4][4];
#pragma unroll
    for (int mi = 0; mi < 4; mi++)
#pragma unroll
        for (int ni = 0; ni < 4; ni++)
#pragma unroll
            for (int c = 0; c < 4; c++) acc[mi][ni][c] = 0.f;

    for (int kc = 0; kc < NTOK; kc += 32) {
#pragma unroll
        for (int it = 0; it < 8; it++) {
            int idx = it * 128 + threadIdx.x;
            int row = idx >> 3, c4 = (idx & 7) * 4;
            float4 v = *(const float4*)&g_S[((size_t)hb * NTOK + q0 + row) * NTOK + kc + c4];
            Ss[row][c4 + 0] = f2tf(v.x); Ss[row][c4 + 1] = f2tf(v.y);
            Ss[row][c4 + 2] = f2tf(v.z); Ss[row][c4 + 3] = f2tf(v.w);
        }
#pragma unroll
        for (int it = 0; it < 4; it++) {
            int idx = it * 128 + threadIdx.x;
            int kr = idx >> 4, d4 = (idx & 15) * 4;
            float4 v = *(const float4*)&buf[(size_t)(kc + kr) * QKV + 512 + h * 64 + d4];
            Vs[kr][d4 + 0] = f2tf(v.x); Vs[kr][d4 + 1] = f2tf(v.y);
            Vs[kr][d4 + 2] = f2tf(v.z); Vs[kr][d4 + 3] = f2tf(v.w);
        }
        __syncthreads();
#pragma unroll
        for (int ks = 0; ks < 4; ks++) {
            int kl = ks * 8;
            unsigned bf[4][2];
#pragma unroll
            for (int ni = 0; ni < 4; ni++) {
                int qr = w * 32 + ni * 8 + g;
                bf[ni][0] = Ss[qr][kl + t];
                bf[ni][1] = Ss[qr][kl + t + 4];
            }
#pragma unroll
            for (int mi = 0; mi < 4; mi++) {
                unsigned a0 = Vs[kl + t][mi * 16 + g];
                unsigned a1 = Vs[kl + t][mi * 16 + g + 8];
                unsigned a2 = Vs[kl + t + 4][mi * 16 + g];
                unsigned a3 = Vs[kl + t + 4][mi * 16 + g + 8];
#pragma unroll
                for (int ni = 0; ni < 4; ni++)
                    mma8(acc[mi][ni][0], acc[mi][ni][1], acc[mi][ni][2], acc[mi][ni][3],
                         a0, a1, a2, a3, bf[ni][0], bf[ni][1]);
            }
        }
        __syncthreads();
    }
    size_t obase = (size_t)bB * NTOK * 256;
#pragma unroll
    for (int mi = 0; mi < 4; mi++)
#pragma unroll
        for (int ni = 0; ni < 4; ni++) {
            int q = q0 + w * 32 + ni * 8 + 2 * t;
            int d = mi * 16 + g;
            float i0 = g_invl[hb * NTOK + q];
            float i1 = g_invl[hb * NTOK + q + 1];
            g_o[obase + (size_t)q * 256 + h * 64 + d]           = acc[mi][ni][0] * i0;
            g_o[obase + (size_t)(q + 1) * 256 + h * 64 + d]     = acc[mi][ni][1] * i1;
            g_o[obase + (size_t)q * 256 + h * 64 + d + 8]       = acc[mi][ni][2] * i0;
            g_o[obase + (size_t)(q + 1) * 256 + h * 64 + d + 8] = acc[mi][ni][3] * i1;
        }
}

// ---------------- fp32 tiled GEMM (saliency + output projections) ------------
__global__ __launch_bounds__(256) void gemm_kernel(
    const float* __restrict__ A, const float* __restrict__ W,
    const float* __restrict__ bias, float* __restrict__ C,
    int M, int Nc, int K, int gelu_flag, int accum)
{
    __shared__ float As[64][68];
    __shared__ float Ws2[64][68];
    int tx = threadIdx.x & 15, ty = threadIdx.x >> 4;
    int n0 = blockIdx.x * 64, m0 = blockIdx.y * 64;
    float acc[4][4];
#pragma unroll
    for (int i = 0; i < 4; i++)
#pragma unroll
        for (int j = 0; j < 4; j++) acc[i][j] = 0.f;

    for (int k0 = 0; k0 < K; k0 += 64) {
        for (int t = threadIdx.x; t < 4096; t += 256) {
            int m = t >> 6, k = t & 63;
            As[k][m] = A[(size_t)(m0 + m) * K + k0 + k];
        }
        for (int t = threadIdx.x; t < 4096; t += 256) {
            int k = t >> 6, n = t & 63;
            Ws2[k][n] = W[(size_t)(k0 + k) * Nc + n0 + n];
        }
        __syncthreads();
#pragma unroll 16
        for (int kk = 0; kk < 64; kk++) {
            float4 a4 = *(const float4*)&As[kk][ty * 4];
            float4 b4 = *(const float4*)&Ws2[kk][tx * 4];
            float a[4] = {a4.x, a4.y, a4.z, a4.w};
            float b[4] = {b4.x, b4.y, b4.z, b4.w};
#pragma unroll
            for (int i = 0; i < 4; i++)
#pragma unroll
                for (int j = 0; j < 4; j++) acc[i][j] += a[i] * b[j];
        }
        __syncthreads();
    }
#pragma unroll
    for (int i = 0; i < 4; i++) {
        int m = m0 + ty * 4 + i;
        float* crow = C + (size_t)m * Nc + n0 + tx * 4;
        float v[4];
#pragma unroll
        for (int j = 0; j < 4; j++) {
            float c = acc[i][j] + bias[n0 + tx * 4 + j];
            if (gelu_flag)
                c = 0.5f * c * (1.0f + erff(c * 0.70710678118654752f));
            v[j] = c;
        }
        if (accum) {
            float4 prev = *(const float4*)crow;
            v[0] += prev.x; v[1] += prev.y; v[2] += prev.z; v[3] += prev.w;
        }
        *(float4*)crow = make_float4(v[0], v[1], v[2], v[3]);
    }
}

// ---------------- saliency scores + exact top-k mask --------------------------
__global__ __launch_bounds__(256) void scores_kernel(
    const float* __restrict__ Ws2, const float* __restrict__ bs2)
{
    int t = blockIdx.x * 8 + (threadIdx.x >> 5);
    int lane = threadIdx.x & 31;
    const float* hp = g_h + (size_t)t * 256;
    float s = 0.f;
    for (int i = lane; i < 256; i += 32) s += hp[i] * Ws2[i];
#pragma unroll
    for (int off = 16; off; off >>= 1) s += __shfl_xor_sync(0xffffffffu, s, off);
    if (lane == 0) g_scores[t] = s + bs2[0];
}

__global__ __launch_bounds__(256) void mask_kernel()
{
    __shared__ float sc[NTOK];
    for (int i = threadIdx.x; i < NTOK; i += 256) sc[i] = g_scores[i];
    __syncthreads();
    int i = blockIdx.x * 256 + threadIdx.x;
    float si = sc[i];
    int cnt = 0;
    for (int j = 0; j < NTOK; j++) {
        float sj = sc[j];
        cnt += (sj > si) || (sj == si && j < i);
    }
    g_mask[i] = (cnt < KSEL) ? 1 : 0;
}

// -----------------------------------------------------------------------------
extern "C" void kernel_launch(void* const* d_in, const int* in_sizes, int n_in,
                              void* d_out, int out_size)
{
    const float* x       = (const float*)d_in[0];
    const float* W_lqkv  = (const float*)d_in[1];
    const float* b_lqkv  = (const float*)d_in[2];
    const float* W_cqkv  = (const float*)d_in[3];
    const float* b_cqkv  = (const float*)d_in[4];
    const float* W_lproj = (const float*)d_in[5];
    const float* b_lproj = (const float*)d_in[6];
    const float* W_cproj = (const float*)d_in[7];
    const float* b_cproj = (const float*)d_in[8];
    const float* W_s1    = (const float*)d_in[9];
    const float* b_s1    = (const float*)d_in[10];
    const float* W_s2    = (const float*)d_in[11];
    const float* b_s2    = (const float*)d_in[12];

    float* out  = (float*)d_out;
    float* attn = out + (size_t)NTOK * DDIM;

    float *p_lqkv, *p_cqkv, *p_h, *p_o;
    cudaGetSymbolAddress((void**)&p_lqkv, g_lqkv);
    cudaGetSymbolAddress((void**)&p_cqkv, g_cqkv);
    cudaGetSymbolAddress((void**)&p_h,    g_h);
    cudaGetSymbolAddress((void**)&p_o,    g_o);

    // QKV projections (tf32 tensor cores)
    proj_tf32<<<dim3(12, 32), 128>>>(x, W_lqkv, b_lqkv, p_lqkv, QKV, DDIM);
    proj_tf32<<<dim3(12, 32), 128>>>(x, W_cqkv, b_cqkv, p_cqkv, QKV, DDIM);

    // saliency path (exact fp32 — guards the top-k boundary)
    gemm_kernel<<<dim3(4, 64), 256>>>(x, W_s1, b_s1, p_h, NTOK, 256, DDIM, 1, 0);
    scores_kernel<<<512, 256>>>(W_s2, b_s2);
    mask_kernel<<<16, 256>>>();

    // attention core
    qk_tf32<<<dim3(32, 32, 8), 128>>>();
    softmax_mean<<<dim3(NTOK, 2), 256>>>(attn);
    pv_tf32<<<dim3(32, 8), 128>>>();

    // output projections (fp32)
    gemm_kernel<<<dim3(8, 64), 256>>>(p_o,              W_lproj, b_lproj, out, NTOK, DDIM, 256, 0, 0);
    gemm_kernel<<<dim3(8, 64), 256>>>(p_o + NTOK * 256, W_cproj, b_cproj, out, NTOK, DDIM, 256, 0, 1);
}

// round 5
// speedup vs baseline: 2.3453x; 1.2357x over previous
#include <cuda_runtime.h>
#include <math.h>

#define NTOK 4096
#define DDIM 512
#define QKV  768
#define KSEL 819

// ---------------- scratch (device globals; no runtime allocation) -------------
__device__ float g_lqkv[NTOK * QKV];
__device__ float g_cqkv[NTOK * QKV];
__device__ float g_h[NTOK * 256];
__device__ float g_scores[NTOK];
__device__ int   g_mask[NTOK];
__device__ float g_m[8 * NTOK];        // final row maxes
__device__ float g_invl[8 * NTOK];     // reciprocal softmax denominators
__device__ float g_o[2 * NTOK * 256];  // per-branch attention outputs

// ---------------- tf32 helpers ------------------------------------------------
__device__ __forceinline__ unsigned f2tf(float f) {
    unsigned r;
    asm("cvt.rna.tf32.f32 %0, %1;" : "=r"(r) : "f"(f));
    return r;
}
__device__ __forceinline__ void mma8(float& c0, float& c1, float& c2, float& c3,
                                     unsigned a0, unsigned a1, unsigned a2, unsigned a3,
                                     unsigned b0, unsigned b1)
{
    asm volatile(
        "mma.sync.aligned.m16n8k8.row.col.f32.tf32.tf32.f32 "
        "{%0,%1,%2,%3},{%4,%5,%6,%7},{%8,%9},{%0,%1,%2,%3};"
        : "+f"(c0), "+f"(c1), "+f"(c2), "+f"(c3)
        : "r"(a0), "r"(a1), "r"(a2), "r"(a3), "r"(b0), "r"(b1));
}

// ---------------- tf32 GEMM: C = A@W + bias (opt accumulate into C) -----------
// block tile 128m x 64n, k-chunk 32; 4 warps, warp tile 32m x 64n
__global__ __launch_bounds__(128) void proj_tf32(
    const float* __restrict__ A, const float* __restrict__ W,
    const float* __restrict__ bias, float* __restrict__ C, int Nc, int K,
    int accum)
{
    __shared__ unsigned Xs[128][36];
    __shared__ unsigned Ws[32][72];
    int t = threadIdx.x & 3, g = (threadIdx.x >> 2) & 7, w = threadIdx.x >> 5;
    int m0 = blockIdx.y * 128, n0 = blockIdx.x * 64;

    float acc[2][8][4];
#pragma unroll
    for (int mi = 0; mi < 2; mi++)
#pragma unroll
        for (int ni = 0; ni < 8; ni++)
#pragma unroll
            for (int c = 0; c < 4; c++) acc[mi][ni][c] = 0.f;

    for (int k0 = 0; k0 < K; k0 += 32) {
#pragma unroll
        for (int it = 0; it < 8; it++) {
            int idx = it * 128 + threadIdx.x;
            int row = idx >> 3, c4 = (idx & 7) * 4;
            float4 v = *(const float4*)&A[(size_t)(m0 + row) * K + k0 + c4];
            Xs[row][c4 + 0] = f2tf(v.x); Xs[row][c4 + 1] = f2tf(v.y);
            Xs[row][c4 + 2] = f2tf(v.z); Xs[row][c4 + 3] = f2tf(v.w);
        }
#pragma unroll
        for (int it = 0; it < 4; it++) {
            int idx = it * 128 + threadIdx.x;
            int kr = idx >> 4, n4 = (idx & 15) * 4;
            float4 v = *(const float4*)&W[(size_t)(k0 + kr) * Nc + n0 + n4];
            Ws[kr][n4 + 0] = f2tf(v.x); Ws[kr][n4 + 1] = f2tf(v.y);
            Ws[kr][n4 + 2] = f2tf(v.z); Ws[kr][n4 + 3] = f2tf(v.w);
        }
        __syncthreads();
#pragma unroll
        for (int ks = 0; ks < 4; ks++) {
            int kl = ks * 8;
            unsigned a[2][4];
#pragma unroll
            for (int mi = 0; mi < 2; mi++) {
                int r = w * 32 + mi * 16 + g;
                a[mi][0] = Xs[r][kl + t];      a[mi][1] = Xs[r + 8][kl + t];
                a[mi][2] = Xs[r][kl + t + 4];  a[mi][3] = Xs[r + 8][kl + t + 4];
            }
#pragma unroll
            for (int ni = 0; ni < 8; ni++) {
                unsigned b0 = Ws[kl + t][ni * 8 + g];
                unsigned b1 = Ws[kl + t + 4][ni * 8 + g];
#pragma unroll
                for (int mi = 0; mi < 2; mi++)
                    mma8(acc[mi][ni][0], acc[mi][ni][1], acc[mi][ni][2], acc[mi][ni][3],
                         a[mi][0], a[mi][1], a[mi][2], a[mi][3], b0, b1);
            }
        }
        __syncthreads();
    }
#pragma unroll
    for (int mi = 0; mi < 2; mi++)
#pragma unroll
        for (int ni = 0; ni < 8; ni++) {
            int m = m0 + w * 32 + mi * 16 + g;
            int n = n0 + ni * 8 + 2 * t;
            float bv0 = bias[n], bv1 = bias[n + 1];
            float v00 = acc[mi][ni][0] + bv0, v01 = acc[mi][ni][1] + bv1;
            float v10 = acc[mi][ni][2] + bv0, v11 = acc[mi][ni][3] + bv1;
            float* p0 = &C[(size_t)m * Nc + n];
            float* p1 = &C[(size_t)(m + 8) * Nc + n];
            if (accum) {
                float2 q0 = *(const float2*)p0, q1 = *(const float2*)p1;
                v00 += q0.x; v01 += q0.y; v10 += q1.x; v11 += q1.y;
            }
            *(float2*)p0 = make_float2(v00, v01);
            *(float2*)p1 = make_float2(v10, v11);
        }
}

// ---------------- flash attention: o, m, invl (no S materialization) ----------
// grid (32 q-tiles, 8 hb), 256 threads = 8 warps, warp owns 16 q-rows
#define FLASH_SMEM ((128*68 + 64*68 + 64*72 + 128*68 + 64) * 4)
__global__ __launch_bounds__(256) void flash_kernel()
{
    extern __shared__ unsigned sm[];
    unsigned* Qs = sm;                 // [128][68]  q x d   (tf32)
    unsigned* Ks = Qs + 128 * 68;      // [64][68]   k x d
    unsigned* Vs = Ks + 64 * 68;       // [64][72]   k x d
    unsigned* Ps = Vs + 64 * 72;       // [128][68]  q x k
    int* maskCh  = (int*)(Ps + 128 * 68);  // [64]

    int hb = blockIdx.y;
    const float* buf = (hb < 4) ? g_lqkv : g_cqkv;
    int h = hb & 3;
    bool content = hb >= 4;
    int q0 = blockIdx.x * 128;
    int tid = threadIdx.x, lane = tid & 31, w = tid >> 5;
    int t = lane & 3, g = lane >> 2;
    int rb = w * 16 + g;              // warp-local base row (+8 for second)

    // load Q tile once
#pragma unroll
    for (int it = 0; it < 8; it++) {
        int idx = it * 256 + tid;
        int r = idx >> 4, c = (idx & 15) * 4;
        float4 v = *(const float4*)&buf[(size_t)(q0 + r) * QKV + h * 64 + c];
        Qs[r * 68 + c + 0] = f2tf(v.x); Qs[r * 68 + c + 1] = f2tf(v.y);
        Qs[r * 68 + c + 2] = f2tf(v.z); Qs[r * 68 + c + 3] = f2tf(v.w);
    }

    float m0 = -1e30f, m1 = -1e30f, l0 = 0.f, l1 = 0.f;
    float oacc[8][4];
#pragma unroll
    for (int ni = 0; ni < 8; ni++)
#pragma unroll
        for (int c = 0; c < 4; c++) oacc[ni][c] = 0.f;

    for (int kc = 0; kc < NTOK; kc += 64) {
        __syncthreads();   // protect Ks/Vs/mask from previous iteration's readers
#pragma unroll
        for (int it = 0; it < 4; it++) {
            int idx = it * 256 + tid;
            int r = idx >> 4, c = (idx & 15) * 4;
            float4 kv = *(const float4*)&buf[(size_t)(kc + r) * QKV + 256 + h * 64 + c];
            Ks[r * 68 + c + 0] = f2tf(kv.x); Ks[r * 68 + c + 1] = f2tf(kv.y);
            Ks[r * 68 + c + 2] = f2tf(kv.z); Ks[r * 68 + c + 3] = f2tf(kv.w);
            float4 vv = *(const float4*)&buf[(size_t)(kc + r) * QKV + 512 + h * 64 + c];
            Vs[r * 72 + c + 0] = f2tf(vv.x); Vs[r * 72 + c + 1] = f2tf(vv.y);
            Vs[r * 72 + c + 2] = f2tf(vv.z); Vs[r * 72 + c + 3] = f2tf(vv.w);
        }
        if (content && tid < 64) maskCh[tid] = g_mask[kc + tid];
        __syncthreads();

        // S tile: 16q x 64k per warp
        float sacc[8][4];
#pragma unroll
        for (int ni = 0; ni < 8; ni++)
#pragma unroll
            for (int c = 0; c < 4; c++) sacc[ni][c] = 0.f;
#pragma unroll
        for (int ks = 0; ks < 8; ks++) {
            int kl = ks * 8;
            unsigned a0 = Qs[rb * 68 + kl + t];
            unsigned a1 = Qs[(rb + 8) * 68 + kl + t];
            unsigned a2 = Qs[rb * 68 + kl + t + 4];
            unsigned a3 = Qs[(rb + 8) * 68 + kl + t + 4];
#pragma unroll
            for (int ni = 0; ni < 8; ni++) {
                unsigned b0 = Ks[(ni * 8 + g) * 68 + kl + t];
                unsigned b1 = Ks[(ni * 8 + g) * 68 + kl + t + 4];
                mma8(sacc[ni][0], sacc[ni][1], sacc[ni][2], sacc[ni][3],
                     a0, a1, a2, a3, b0, b1);
            }
        }
        // scale + mask + chunk max
        float cm0 = -1e30f, cm1 = -1e30f;
#pragma unroll
        for (int ni = 0; ni < 8; ni++) {
            int c0 = ni * 8 + 2 * t;
            bool on0 = !content || maskCh[c0];
            bool on1 = !content || maskCh[c0 + 1];
            sacc[ni][0] *= 0.125f; sacc[ni][1] *= 0.125f;
            sacc[ni][2] *= 0.125f; sacc[ni][3] *= 0.125f;
            cm0 = fmaxf(cm0, fmaxf(on0 ? sacc[ni][0] : -1e30f, on1 ? sacc[ni][1] : -1e30f));
            cm1 = fmaxf(cm1, fmaxf(on0 ? sacc[ni][2] : -1e30f, on1 ? sacc[ni][3] : -1e30f));
        }
        cm0 = fmaxf(cm0, __shfl_xor_sync(0xffffffffu, cm0, 1));
        cm0 = fmaxf(cm0, __shfl_xor_sync(0xffffffffu, cm0, 2));
        cm1 = fmaxf(cm1, __shfl_xor_sync(0xffffffffu, cm1, 1));
        cm1 = fmaxf(cm1, __shfl_xor_sync(0xffffffffu, cm1, 2));

        float mn0 = fmaxf(m0, cm0), mn1 = fmaxf(m1, cm1);
        float r0 = __expf(m0 - mn0), r1 = __expf(m1 - mn1);
        m0 = mn0; m1 = mn1;

        float es0 = 0.f, es1 = 0.f;
#pragma unroll
        for (int ni = 0; ni < 8; ni++) {
            int c0 = ni * 8 + 2 * t;
            bool on0 = !content || maskCh[c0];
            bool on1 = !content || maskCh[c0 + 1];
            float e00 = on0 ? __expf(sacc[ni][0] - mn0) : 0.f;
            float e01 = on1 ? __expf(sacc[ni][1] - mn0) : 0.f;
            float e10 = on0 ? __expf(sacc[ni][2] - mn1) : 0.f;
            float e11 = on1 ? __expf(sacc[ni][3] - mn1) : 0.f;
            es0 += e00 + e01; es1 += e10 + e11;
            Ps[rb * 68 + c0]           = f2tf(e00);
            Ps[rb * 68 + c0 + 1]       = f2tf(e01);
            Ps[(rb + 8) * 68 + c0]     = f2tf(e10);
            Ps[(rb + 8) * 68 + c0 + 1] = f2tf(e11);
        }
        es0 += __shfl_xor_sync(0xffffffffu, es0, 1);
        es0 += __shfl_xor_sync(0xffffffffu, es0, 2);
        es1 += __shfl_xor_sync(0xffffffffu, es1, 1);
        es1 += __shfl_xor_sync(0xffffffffu, es1, 2);
        l0 = l0 * r0 + es0;
        l1 = l1 * r1 + es1;
#pragma unroll
        for (int ni = 0; ni < 8; ni++) {
            oacc[ni][0] *= r0; oacc[ni][1] *= r0;
            oacc[ni][2] *= r1; oacc[ni][3] *= r1;
        }
        __syncwarp();

        // PV: 16q x 64d per warp
#pragma unroll
        for (int ks = 0; ks < 8; ks++) {
            int kl = ks * 8;
            unsigned a0 = Ps[rb * 68 + kl + t];
            unsigned a1 = Ps[(rb + 8) * 68 + kl + t];
            unsigned a2 = Ps[rb * 68 + kl + t + 4];
            unsigned a3 = Ps[(rb + 8) * 68 + kl + t + 4];
#pragma unroll
            for (int ni = 0; ni < 8; ni++) {
                unsigned b0 = Vs[(kl + t) * 72 + ni * 8 + g];
                unsigned b1 = Vs[(kl + t + 4) * 72 + ni * 8 + g];
                mma8(oacc[ni][0], oacc[ni][1], oacc[ni][2], oacc[ni][3],
                     a0, a1, a2, a3, b0, b1);
            }
        }
    }

    float iv0 = 1.0f / l0, iv1 = 1.0f / l1;
    int bB = hb >> 2;
    size_t ob = (size_t)bB * NTOK * 256;
    int r0i = q0 + rb, r1i = r0i + 8;
#pragma unroll
    for (int ni = 0; ni < 8; ni++) {
        int d = h * 64 + ni * 8 + 2 * t;
        *(float2*)&g_o[ob + (size_t)r0i * 256 + d] =
            make_float2(oacc[ni][0] * iv0, oacc[ni][1] * iv0);
        *(float2*)&g_o[ob + (size_t)r1i * 256 + d] =
            make_float2(oacc[ni][2] * iv1, oacc[ni][3] * iv1);
    }
    if (t == 0) {
        g_invl[hb * NTOK + r0i] = iv0; g_invl[hb * NTOK + r1i] = iv1;
        g_m[hb * NTOK + r0i] = m0;     g_m[hb * NTOK + r1i] = m1;
    }
}

// ---------------- attn output: recompute logits, mean of probs over heads -----
// grid (32 k-tiles, 32 q-tiles, 2 branch), 256 threads = 8 warps
#define ATTN_SMEM ((128*68 + 128*68 + 128) * 4)
__global__ __launch_bounds__(256) void attn_kernel(float* __restrict__ attn)
{
    extern __shared__ unsigned sm[];
    unsigned* Qs = sm;                 // [128][68]
    unsigned* Ks = Qs + 128 * 68;      // [128][68]
    int* mk = (int*)(Ks + 128 * 68);   // [128]

    int b = blockIdx.z;
    const float* buf = b ? g_cqkv : g_lqkv;
    int q0 = blockIdx.y * 128, k0 = blockIdx.x * 128;
    int tid = threadIdx.x, lane = tid & 31, w = tid >> 5;
    int t = lane & 3, g = lane >> 2;
    int rb = w * 16 + g;
    int r0i = q0 + rb, r1i = r0i + 8;

    if (b && tid < 128) mk[tid] = g_mask[k0 + tid];

    float mh[4][2], iv[4][2];
#pragma unroll
    for (int h = 0; h < 4; h++) {
        mh[h][0] = g_m[(b * 4 + h) * NTOK + r0i];
        mh[h][1] = g_m[(b * 4 + h) * NTOK + r1i];
        iv[h][0] = g_invl[(b * 4 + h) * NTOK + r0i];
        iv[h][1] = g_invl[(b * 4 + h) * NTOK + r1i];
    }

    float facc[16][4];
#pragma unroll
    for (int ni = 0; ni < 16; ni++)
#pragma unroll
        for (int c = 0; c < 4; c++) facc[ni][c] = 0.f;

    for (int h = 0; h < 4; h++) {
        __syncthreads();
#pragma unroll
        for (int it = 0; it < 8; it++) {
            int idx = it * 256 + tid;
            int r = idx >> 4, c = (idx & 15) * 4;
            float4 v = *(const float4*)&buf[(size_t)(q0 + r) * QKV + h * 64 + c];
            Qs[r * 68 + c + 0] = f2tf(v.x); Qs[r * 68 + c + 1] = f2tf(v.y);
            Qs[r * 68 + c + 2] = f2tf(v.z); Qs[r * 68 + c + 3] = f2tf(v.w);
            float4 u = *(const float4*)&buf[(size_t)(k0 + r) * QKV + 256 + h * 64 + c];
            Ks[r * 68 + c + 0] = f2tf(u.x); Ks[r * 68 + c + 1] = f2tf(u.y);
            Ks[r * 68 + c + 2] = f2tf(u.z); Ks[r * 68 + c + 3] = f2tf(u.w);
        }
        __syncthreads();

        float sacc[16][4];
#pragma unroll
        for (int ni = 0; ni < 16; ni++)
#pragma unroll
            for (int c = 0; c < 4; c++) sacc[ni][c] = 0.f;
#pragma unroll
        for (int ks = 0; ks < 8; ks++) {
            int kl = ks * 8;
            unsigned a0 = Qs[rb * 68 + kl + t];
            unsigned a1 = Qs[(rb + 8) * 68 + kl + t];
            unsigned a2 = Qs[rb * 68 + kl + t + 4];
            unsigned a3 = Qs[(rb + 8) * 68 + kl + t + 4];
#pragma unroll
            for (int ni = 0; ni < 16; ni++) {
                unsigned b0 = Ks[(ni * 8 + g) * 68 + kl + t];
                unsigned b1 = Ks[(ni * 8 + g) * 68 + kl + t + 4];
                mma8(sacc[ni][0], sacc[ni][1], sacc[ni][2], sacc[ni][3],
                     a0, a1, a2, a3, b0, b1);
            }
        }
#pragma unroll
        for (int ni = 0; ni < 16; ni++) {
            int c0 = ni * 8 + 2 * t;
            bool on0 = !b || mk[c0];
            bool on1 = !b || mk[c0 + 1];
            facc[ni][0] += on0 ? __expf(sacc[ni][0] * 0.125f - mh[h][0]) * iv[h][0] : 0.f;
            facc[ni][1] += on1 ? __expf(sacc[ni][1] * 0.125f - mh[h][0]) * iv[h][0] : 0.f;
            facc[ni][2] += on0 ? __expf(sacc[ni][2] * 0.125f - mh[h][1]) * iv[h][1] : 0.f;
            facc[ni][3] += on1 ? __expf(sacc[ni][3] * 0.125f - mh[h][1]) * iv[h][1] : 0.f;
        }
    }
#pragma unroll
    for (int ni = 0; ni < 16; ni++) {
        int kk = k0 + ni * 8 + 2 * t;
        *(float2*)&attn[((size_t)(b * NTOK + r0i)) * NTOK + kk] =
            make_float2(facc[ni][0] * 0.25f, facc[ni][1] * 0.25f);
        *(float2*)&attn[((size_t)(b * NTOK + r1i)) * NTOK + kk] =
            make_float2(facc[ni][2] * 0.25f, facc[ni][3] * 0.25f);
    }
}

// ---------------- fp32 tiled GEMM (saliency s1, exact) ------------------------
__global__ __launch_bounds__(256) void gemm_kernel(
    const float* __restrict__ A, const float* __restrict__ W,
    const float* __restrict__ bias, float* __restrict__ C,
    int M, int Nc, int K, int gelu_flag, int accum)
{
    __shared__ float As[64][68];
    __shared__ float Ws2[64][68];
    int tx = threadIdx.x & 15, ty = threadIdx.x >> 4;
    int n0 = blockIdx.x * 64, m0 = blockIdx.y * 64;
    float acc[4][4];
#pragma unroll
    for (int i = 0; i < 4; i++)
#pragma unroll
        for (int j = 0; j < 4; j++) acc[i][j] = 0.f;

    for (int k0 = 0; k0 < K; k0 += 64) {
        for (int t = threadIdx.x; t < 4096; t += 256) {
            int m = t >> 6, k = t & 63;
            As[k][m] = A[(size_t)(m0 + m) * K + k0 + k];
        }
        for (int t = threadIdx.x; t < 4096; t += 256) {
            int k = t >> 6, n = t & 63;
            Ws2[k][n] = W[(size_t)(k0 + k) * Nc + n0 + n];
        }
        __syncthreads();
#pragma unroll 16
        for (int kk = 0; kk < 64; kk++) {
            float4 a4 = *(const float4*)&As[kk][ty * 4];
            float4 b4 = *(const float4*)&Ws2[kk][tx * 4];
            float a[4] = {a4.x, a4.y, a4.z, a4.w};
            float b[4] = {b4.x, b4.y, b4.z, b4.w};
#pragma unroll
            for (int i = 0; i < 4; i++)
#pragma unroll
                for (int j = 0; j < 4; j++) acc[i][j] += a[i] * b[j];
        }
        __syncthreads();
    }
#pragma unroll
    for (int i = 0; i < 4; i++) {
        int m = m0 + ty * 4 + i;
        float* crow = C + (size_t)m * Nc + n0 + tx * 4;
        float v[4];
#pragma unroll
        for (int j = 0; j < 4; j++) {
            float c = acc[i][j] + bias[n0 + tx * 4 + j];
            if (gelu_flag)
                c = 0.5f * c * (1.0f + erff(c * 0.70710678118654752f));
            v[j] = c;
        }
        if (accum) {
            float4 prev = *(const float4*)crow;
            v[0] += prev.x; v[1] += prev.y; v[2] += prev.z; v[3] += prev.w;
        }
        *(float4*)crow = make_float4(v[0], v[1], v[2], v[3]);
    }
}

// ---------------- saliency scores + exact top-k mask --------------------------
__global__ __launch_bounds__(256) void scores_kernel(
    const float* __restrict__ Ws2, const float* __restrict__ bs2)
{
    int t = blockIdx.x * 8 + (threadIdx.x >> 5);
    int lane = threadIdx.x & 31;
    const float* hp = g_h + (size_t)t * 256;
    float s = 0.f;
    for (int i = lane; i < 256; i += 32) s += hp[i] * Ws2[i];
#pragma unroll
    for (int off = 16; off; off >>= 1) s += __shfl_xor_sync(0xffffffffu, s, off);
    if (lane == 0) g_scores[t] = s + bs2[0];
}

__global__ __launch_bounds__(256) void mask_kernel()
{
    __shared__ float sc[NTOK];
    for (int i = threadIdx.x; i < NTOK; i += 256) sc[i] = g_scores[i];
    __syncthreads();
    int i = blockIdx.x * 256 + threadIdx.x;
    float si = sc[i];
    int cnt = 0;
    for (int j = 0; j < NTOK; j++) {
        float sj = sc[j];
        cnt += (sj > si) || (sj == si && j < i);
    }
    g_mask[i] = (cnt < KSEL) ? 1 : 0;
}

// -----------------------------------------------------------------------------
extern "C" void kernel_launch(void* const* d_in, const int* in_sizes, int n_in,
                              void* d_out, int out_size)
{
    const float* x       = (const float*)d_in[0];
    const float* W_lqkv  = (const float*)d_in[1];
    const float* b_lqkv  = (const float*)d_in[2];
    const float* W_cqkv  = (const float*)d_in[3];
    const float* b_cqkv  = (const float*)d_in[4];
    const float* W_lproj = (const float*)d_in[5];
    const float* b_lproj = (const float*)d_in[6];
    const float* W_cproj = (const float*)d_in[7];
    const float* b_cproj = (const float*)d_in[8];
    const float* W_s1    = (const float*)d_in[9];
    const float* b_s1    = (const float*)d_in[10];
    const float* W_s2    = (const float*)d_in[11];
    const float* b_s2    = (const float*)d_in[12];

    float* out  = (float*)d_out;
    float* attn = out + (size_t)NTOK * DDIM;

    float *p_lqkv, *p_cqkv, *p_h, *p_o;
    cudaGetSymbolAddress((void**)&p_lqkv, g_lqkv);
    cudaGetSymbolAddress((void**)&p_cqkv, g_cqkv);
    cudaGetSymbolAddress((void**)&p_h,    g_h);
    cudaGetSymbolAddress((void**)&p_o,    g_o);

    static int attr_done = 0;
    if (!attr_done) {
        cudaFuncSetAttribute(flash_kernel,
            cudaFuncAttributeMaxDynamicSharedMemorySize, FLASH_SMEM);
        cudaFuncSetAttribute(attn_kernel,
            cudaFuncAttributeMaxDynamicSharedMemorySize, ATTN_SMEM);
        attr_done = 1;
    }

    // QKV projections (tf32 tensor cores)
    proj_tf32<<<dim3(12, 32), 128>>>(x, W_lqkv, b_lqkv, p_lqkv, QKV, DDIM, 0);
    proj_tf32<<<dim3(12, 32), 128>>>(x, W_cqkv, b_cqkv, p_cqkv, QKV, DDIM, 0);

    // saliency path (exact fp32 — guards the top-k boundary)
    gemm_kernel<<<dim3(4, 64), 256>>>(x, W_s1, b_s1, p_h, NTOK, 256, DDIM, 1, 0);
    scores_kernel<<<512, 256>>>(W_s2, b_s2);
    mask_kernel<<<16, 256>>>();

    // attention core (flash, no S materialization)
    flash_kernel<<<dim3(32, 8), 256, FLASH_SMEM>>>();

    // attn output (recompute logits, write head-mean of probabilities)
    attn_kernel<<<dim3(32, 32, 2), 256, ATTN_SMEM>>>(attn);

    // output projections (tf32, accumulate branches)
    proj_tf32<<<dim3(8, 32), 128>>>(p_o,              W_lproj, b_lproj, out, DDIM, 256, 0);
    proj_tf32<<<dim3(8, 32), 128>>>(p_o + NTOK * 256, W_cproj, b_cproj, out, DDIM, 256, 1);
}

// round 6
// speedup vs baseline: 3.2127x; 1.3699x over previous
#include <cuda_runtime.h>
#include <math.h>

#define NTOK 4096
#define DDIM 512
#define QKV  768
#define KSEL 819
#define SELPAD 832          // KSEL padded to multiple of 64
#define NCHUNK_C 13         // SELPAD / 64

// ---------------- scratch (device globals; no runtime allocation) -------------
__device__ float g_lqkv[NTOK * QKV];
__device__ float g_cqkv[NTOK * QKV];
__device__ float g_h[NTOK * 256];
__device__ float g_scores[NTOK];
__device__ int   g_mask[NTOK];
__device__ int   g_sel[SELPAD];        // compacted selected indices, -1 pad
__device__ float g_m[8 * NTOK];        // final row maxes
__device__ float g_invl[8 * NTOK];     // reciprocal softmax denominators
__device__ float g_o[2 * NTOK * 256];  // per-branch attention outputs

// ---------------- tf32 helpers ------------------------------------------------
__device__ __forceinline__ unsigned f2tf(float f) {
    unsigned r;
    asm("cvt.rna.tf32.f32 %0, %1;" : "=r"(r) : "f"(f));
    return r;
}
__device__ __forceinline__ void mma8(float& c0, float& c1, float& c2, float& c3,
                                     unsigned a0, unsigned a1, unsigned a2, unsigned a3,
                                     unsigned b0, unsigned b1)
{
    asm volatile(
        "mma.sync.aligned.m16n8k8.row.col.f32.tf32.tf32.f32 "
        "{%0,%1,%2,%3},{%4,%5,%6,%7},{%8,%9},{%0,%1,%2,%3};"
        : "+f"(c0), "+f"(c1), "+f"(c2), "+f"(c3)
        : "r"(a0), "r"(a1), "r"(a2), "r"(a3), "r"(b0), "r"(b1));
}

// ---------------- tf32 GEMM: C = A@W + bias (opt accumulate into C) -----------
__global__ __launch_bounds__(128) void proj_tf32(
    const float* __restrict__ A, const float* __restrict__ W,
    const float* __restrict__ bias, float* __restrict__ C, int Nc, int K,
    int accum)
{
    __shared__ unsigned Xs[128][36];
    __shared__ unsigned Ws[32][72];
    int t = threadIdx.x & 3, g = (threadIdx.x >> 2) & 7, w = threadIdx.x >> 5;
    int m0 = blockIdx.y * 128, n0 = blockIdx.x * 64;

    float acc[2][8][4];
#pragma unroll
    for (int mi = 0; mi < 2; mi++)
#pragma unroll
        for (int ni = 0; ni < 8; ni++)
#pragma unroll
            for (int c = 0; c < 4; c++) acc[mi][ni][c] = 0.f;

    for (int k0 = 0; k0 < K; k0 += 32) {
#pragma unroll
        for (int it = 0; it < 8; it++) {
            int idx = it * 128 + threadIdx.x;
            int row = idx >> 3, c4 = (idx & 7) * 4;
            float4 v = *(const float4*)&A[(size_t)(m0 + row) * K + k0 + c4];
            Xs[row][c4 + 0] = f2tf(v.x); Xs[row][c4 + 1] = f2tf(v.y);
            Xs[row][c4 + 2] = f2tf(v.z); Xs[row][c4 + 3] = f2tf(v.w);
        }
#pragma unroll
        for (int it = 0; it < 4; it++) {
            int idx = it * 128 + threadIdx.x;
            int kr = idx >> 4, n4 = (idx & 15) * 4;
            float4 v = *(const float4*)&W[(size_t)(k0 + kr) * Nc + n0 + n4];
            Ws[kr][n4 + 0] = f2tf(v.x); Ws[kr][n4 + 1] = f2tf(v.y);
            Ws[kr][n4 + 2] = f2tf(v.z); Ws[kr][n4 + 3] = f2tf(v.w);
        }
        __syncthreads();
#pragma unroll
        for (int ks = 0; ks < 4; ks++) {
            int kl = ks * 8;
            unsigned a[2][4];
#pragma unroll
            for (int mi = 0; mi < 2; mi++) {
                int r = w * 32 + mi * 16 + g;
                a[mi][0] = Xs[r][kl + t];      a[mi][1] = Xs[r + 8][kl + t];
                a[mi][2] = Xs[r][kl + t + 4];  a[mi][3] = Xs[r + 8][kl + t + 4];
            }
#pragma unroll
            for (int ni = 0; ni < 8; ni++) {
                unsigned b0 = Ws[kl + t][ni * 8 + g];
                unsigned b1 = Ws[kl + t + 4][ni * 8 + g];
#pragma unroll
                for (int mi = 0; mi < 2; mi++)
                    mma8(acc[mi][ni][0], acc[mi][ni][1], acc[mi][ni][2], acc[mi][ni][3],
                         a[mi][0], a[mi][1], a[mi][2], a[mi][3], b0, b1);
            }
        }
        __syncthreads();
    }
#pragma unroll
    for (int mi = 0; mi < 2; mi++)
#pragma unroll
        for (int ni = 0; ni < 8; ni++) {
            int m = m0 + w * 32 + mi * 16 + g;
            int n = n0 + ni * 8 + 2 * t;
            float bv0 = bias[n], bv1 = bias[n + 1];
            float v00 = acc[mi][ni][0] + bv0, v01 = acc[mi][ni][1] + bv1;
            float v10 = acc[mi][ni][2] + bv0, v11 = acc[mi][ni][3] + bv1;
            float* p0 = &C[(size_t)m * Nc + n];
            float* p1 = &C[(size_t)(m + 8) * Nc + n];
            if (accum) {
                float2 q0 = *(const float2*)p0, q1 = *(const float2*)p1;
                v00 += q0.x; v01 += q0.y; v10 += q1.x; v11 += q1.y;
            }
            *(float2*)p0 = make_float2(v00, v01);
            *(float2*)p1 = make_float2(v10, v11);
        }
}

// ---------------- flash attention (content heads walk compacted keys) ---------
#define FLASH_SMEM ((128*68 + 64*68 + 64*72 + 128*68 + 64) * 4)
__global__ __launch_bounds__(256) void flash_kernel()
{
    extern __shared__ unsigned sm[];
    unsigned* Qs = sm;                 // [128][68]
    unsigned* Ks = Qs + 128 * 68;      // [64][68]
    unsigned* Vs = Ks + 64 * 68;       // [64][72]
    unsigned* Ps = Vs + 64 * 72;       // [128][68]
    int* maskCh  = (int*)(Ps + 128 * 68);  // [64]

    int hb = blockIdx.y;
    const float* buf = (hb < 4) ? g_lqkv : g_cqkv;
    int h = hb & 3;
    bool content = hb >= 4;
    int q0 = blockIdx.x * 128;
    int tid = threadIdx.x, lane = tid & 31, w = tid >> 5;
    int t = lane & 3, g = lane >> 2;
    int rb = w * 16 + g;

#pragma unroll
    for (int it = 0; it < 8; it++) {
        int idx = it * 256 + tid;
        int r = idx >> 4, c = (idx & 15) * 4;
        float4 v = *(const float4*)&buf[(size_t)(q0 + r) * QKV + h * 64 + c];
        Qs[r * 68 + c + 0] = f2tf(v.x); Qs[r * 68 + c + 1] = f2tf(v.y);
        Qs[r * 68 + c + 2] = f2tf(v.z); Qs[r * 68 + c + 3] = f2tf(v.w);
    }

    float m0 = -1e30f, m1 = -1e30f, l0 = 0.f, l1 = 0.f;
    float oacc[8][4];
#pragma unroll
    for (int ni = 0; ni < 8; ni++)
#pragma unroll
        for (int c = 0; c < 4; c++) oacc[ni][c] = 0.f;

    int nch = content ? NCHUNK_C : (NTOK / 64);
    for (int ch = 0; ch < nch; ch++) {
        int kc = ch * 64;
        __syncthreads();
#pragma unroll
        for (int it = 0; it < 4; it++) {
            int idx = it * 256 + tid;
            int r = idx >> 4, c = (idx & 15) * 4;
            int srow = content ? g_sel[kc + r] : (kc + r);
            int rr = srow < 0 ? 0 : srow;
            float4 kv = *(const float4*)&buf[(size_t)rr * QKV + 256 + h * 64 + c];
            Ks[r * 68 + c + 0] = f2tf(kv.x); Ks[r * 68 + c + 1] = f2tf(kv.y);
            Ks[r * 68 + c + 2] = f2tf(kv.z); Ks[r * 68 + c + 3] = f2tf(kv.w);
            float4 vv = *(const float4*)&buf[(size_t)rr * QKV + 512 + h * 64 + c];
            Vs[r * 72 + c + 0] = f2tf(vv.x); Vs[r * 72 + c + 1] = f2tf(vv.y);
            Vs[r * 72 + c + 2] = f2tf(vv.z); Vs[r * 72 + c + 3] = f2tf(vv.w);
        }
        if (tid < 64) maskCh[tid] = content ? (g_sel[kc + tid] >= 0) : 1;
        __syncthreads();

        float sacc[8][4];
#pragma unroll
        for (int ni = 0; ni < 8; ni++)
#pragma unroll
            for (int c = 0; c < 4; c++) sacc[ni][c] = 0.f;
#pragma unroll
        for (int ks = 0; ks < 8; ks++) {
            int kl = ks * 8;
            unsigned a0 = Qs[rb * 68 + kl + t];
            unsigned a1 = Qs[(rb + 8) * 68 + kl + t];
            unsigned a2 = Qs[rb * 68 + kl + t + 4];
            unsigned a3 = Qs[(rb + 8) * 68 + kl + t + 4];
#pragma unroll
            for (int ni = 0; ni < 8; ni++) {
                unsigned b0 = Ks[(ni * 8 + g) * 68 + kl + t];
                unsigned b1 = Ks[(ni * 8 + g) * 68 + kl + t + 4];
                mma8(sacc[ni][0], sacc[ni][1], sacc[ni][2], sacc[ni][3],
                     a0, a1, a2, a3, b0, b1);
            }
        }
        float cm0 = -1e30f, cm1 = -1e30f;
#pragma unroll
        for (int ni = 0; ni < 8; ni++) {
            int c0 = ni * 8 + 2 * t;
            bool on0 = maskCh[c0];
            bool on1 = maskCh[c0 + 1];
            sacc[ni][0] *= 0.125f; sacc[ni][1] *= 0.125f;
            sacc[ni][2] *= 0.125f; sacc[ni][3] *= 0.125f;
            cm0 = fmaxf(cm0, fmaxf(on0 ? sacc[ni][0] : -1e30f, on1 ? sacc[ni][1] : -1e30f));
            cm1 = fmaxf(cm1, fmaxf(on0 ? sacc[ni][2] : -1e30f, on1 ? sacc[ni][3] : -1e30f));
        }
        cm0 = fmaxf(cm0, __shfl_xor_sync(0xffffffffu, cm0, 1));
        cm0 = fmaxf(cm0, __shfl_xor_sync(0xffffffffu, cm0, 2));
        cm1 = fmaxf(cm1, __shfl_xor_sync(0xffffffffu, cm1, 1));
        cm1 = fmaxf(cm1, __shfl_xor_sync(0xffffffffu, cm1, 2));

        float mn0 = fmaxf(m0, cm0), mn1 = fmaxf(m1, cm1);
        float r0 = __expf(m0 - mn0), r1 = __expf(m1 - mn1);
        m0 = mn0; m1 = mn1;

        float es0 = 0.f, es1 = 0.f;
#pragma unroll
        for (int ni = 0; ni < 8; ni++) {
            int c0 = ni * 8 + 2 * t;
            bool on0 = maskCh[c0];
            bool on1 = maskCh[c0 + 1];
            float e00 = on0 ? __expf(sacc[ni][0] - mn0) : 0.f;
            float e01 = on1 ? __expf(sacc[ni][1] - mn0) : 0.f;
            float e10 = on0 ? __expf(sacc[ni][2] - mn1) : 0.f;
            float e11 = on1 ? __expf(sacc[ni][3] - mn1) : 0.f;
            es0 += e00 + e01; es1 += e10 + e11;
            Ps[rb * 68 + c0]           = f2tf(e00);
            Ps[rb * 68 + c0 + 1]       = f2tf(e01);
            Ps[(rb + 8) * 68 + c0]     = f2tf(e10);
            Ps[(rb + 8) * 68 + c0 + 1] = f2tf(e11);
        }
        es0 += __shfl_xor_sync(0xffffffffu, es0, 1);
        es0 += __shfl_xor_sync(0xffffffffu, es0, 2);
        es1 += __shfl_xor_sync(0xffffffffu, es1, 1);
        es1 += __shfl_xor_sync(0xffffffffu, es1, 2);
        l0 = l0 * r0 + es0;
        l1 = l1 * r1 + es1;
#pragma unroll
        for (int ni = 0; ni < 8; ni++) {
            oacc[ni][0] *= r0; oacc[ni][1] *= r0;
            oacc[ni][2] *= r1; oacc[ni][3] *= r1;
        }
        __syncwarp();

#pragma unroll
        for (int ks = 0; ks < 8; ks++) {
            int kl = ks * 8;
            unsigned a0 = Ps[rb * 68 + kl + t];
            unsigned a1 = Ps[(rb + 8) * 68 + kl + t];
            unsigned a2 = Ps[rb * 68 + kl + t + 4];
            unsigned a3 = Ps[(rb + 8) * 68 + kl + t + 4];
#pragma unroll
            for (int ni = 0; ni < 8; ni++) {
                unsigned b0 = Vs[(kl + t) * 72 + ni * 8 + g];
                unsigned b1 = Vs[(kl + t + 4) * 72 + ni * 8 + g];
                mma8(oacc[ni][0], oacc[ni][1], oacc[ni][2], oacc[ni][3],
                     a0, a1, a2, a3, b0, b1);
            }
        }
    }

    float iv0 = 1.0f / l0, iv1 = 1.0f / l1;
    int bB = hb >> 2;
    size_t ob = (size_t)bB * NTOK * 256;
    int r0i = q0 + rb, r1i = r0i + 8;
#pragma unroll
    for (int ni = 0; ni < 8; ni++) {
        int d = h * 64 + ni * 8 + 2 * t;
        *(float2*)&g_o[ob + (size_t)r0i * 256 + d] =
            make_float2(oacc[ni][0] * iv0, oacc[ni][1] * iv0);
        *(float2*)&g_o[ob + (size_t)r1i * 256 + d] =
            make_float2(oacc[ni][2] * iv1, oacc[ni][3] * iv1);
    }
    if (t == 0) {
        g_invl[hb * NTOK + r0i] = iv0; g_invl[hb * NTOK + r1i] = iv1;
        g_m[hb * NTOK + r0i] = m0;     g_m[hb * NTOK + r1i] = m1;
    }
}

// ---------------- attn local half: dense recompute + head-mean ----------------
#define ATTNL_SMEM ((128*68 + 128*68) * 4)
__global__ __launch_bounds__(256) void attn_local(float* __restrict__ attn)
{
    extern __shared__ unsigned sm[];
    unsigned* Qs = sm;                 // [128][68]
    unsigned* Ks = Qs + 128 * 68;      // [128][68]

    const float* buf = g_lqkv;
    int q0 = blockIdx.y * 128, k0 = blockIdx.x * 128;
    int tid = threadIdx.x, lane = tid & 31, w = tid >> 5;
    int t = lane & 3, g = lane >> 2;
    int rb = w * 16 + g;
    int r0i = q0 + rb, r1i = r0i + 8;

    float mh[4][2], iv[4][2];
#pragma unroll
    for (int h = 0; h < 4; h++) {
        mh[h][0] = g_m[h * NTOK + r0i];
        mh[h][1] = g_m[h * NTOK + r1i];
        iv[h][0] = g_invl[h * NTOK + r0i];
        iv[h][1] = g_invl[h * NTOK + r1i];
    }

    float facc[16][4];
#pragma unroll
    for (int ni = 0; ni < 16; ni++)
#pragma unroll
        for (int c = 0; c < 4; c++) facc[ni][c] = 0.f;

    for (int h = 0; h < 4; h++) {
        __syncthreads();
#pragma unroll
        for (int it = 0; it < 8; it++) {
            int idx = it * 256 + tid;
            int r = idx >> 4, c = (idx & 15) * 4;
            float4 v = *(const float4*)&buf[(size_t)(q0 + r) * QKV + h * 64 + c];
            Qs[r * 68 + c + 0] = f2tf(v.x); Qs[r * 68 + c + 1] = f2tf(v.y);
            Qs[r * 68 + c + 2] = f2tf(v.z); Qs[r * 68 + c + 3] = f2tf(v.w);
            float4 u = *(const float4*)&buf[(size_t)(k0 + r) * QKV + 256 + h * 64 + c];
            Ks[r * 68 + c + 0] = f2tf(u.x); Ks[r * 68 + c + 1] = f2tf(u.y);
            Ks[r * 68 + c + 2] = f2tf(u.z); Ks[r * 68 + c + 3] = f2tf(u.w);
        }
        __syncthreads();

        float sacc[16][4];
#pragma unroll
        for (int ni = 0; ni < 16; ni++)
#pragma unroll
            for (int c = 0; c < 4; c++) sacc[ni][c] = 0.f;
#pragma unroll
        for (int ks = 0; ks < 8; ks++) {
            int kl = ks * 8;
            unsigned a0 = Qs[rb * 68 + kl + t];
            unsigned a1 = Qs[(rb + 8) * 68 + kl + t];
            unsigned a2 = Qs[rb * 68 + kl + t + 4];
            unsigned a3 = Qs[(rb + 8) * 68 + kl + t + 4];
#pragma unroll
            for (int ni = 0; ni < 16; ni++) {
                unsigned b0 = Ks[(ni * 8 + g) * 68 + kl + t];
                unsigned b1 = Ks[(ni * 8 + g) * 68 + kl + t + 4];
                mma8(sacc[ni][0], sacc[ni][1], sacc[ni][2], sacc[ni][3],
                     a0, a1, a2, a3, b0, b1);
            }
        }
#pragma unroll
        for (int ni = 0; ni < 16; ni++) {
            facc[ni][0] += __expf(sacc[ni][0] * 0.125f - mh[h][0]) * iv[h][0];
            facc[ni][1] += __expf(sacc[ni][1] * 0.125f - mh[h][0]) * iv[h][0];
            facc[ni][2] += __expf(sacc[ni][2] * 0.125f - mh[h][1]) * iv[h][1];
            facc[ni][3] += __expf(sacc[ni][3] * 0.125f - mh[h][1]) * iv[h][1];
        }
    }
#pragma unroll
    for (int ni = 0; ni < 16; ni++) {
        int kk = k0 + ni * 8 + 2 * t;
        *(float2*)&attn[(size_t)r0i * NTOK + kk] =
            make_float2(facc[ni][0] * 0.25f, facc[ni][1] * 0.25f);
        *(float2*)&attn[(size_t)r1i * NTOK + kk] =
            make_float2(facc[ni][2] * 0.25f, facc[ni][3] * 0.25f);
    }
}

// ---------------- attn content half: only selected columns --------------------
#define ATTNC_SMEM ((128*68 + 64*68 + 64) * 4)
__global__ __launch_bounds__(256) void attn_content(float* __restrict__ attn)
{
    extern __shared__ unsigned sm[];
    unsigned* Qs = sm;                 // [128][68]
    unsigned* Ks = Qs + 128 * 68;      // [64][68]
    int* selS    = (int*)(Ks + 64 * 68);   // [64]

    const float* buf = g_cqkv;
    int q0 = blockIdx.y * 128;
    int k0s = blockIdx.x * 64;         // offset into sel list
    int tid = threadIdx.x, lane = tid & 31, w = tid >> 5;
    int t = lane & 3, g = lane >> 2;
    int rb = w * 16 + g;
    int r0i = q0 + rb, r1i = r0i + 8;

    if (tid < 64) selS[tid] = g_sel[k0s + tid];

    float mh[4][2], iv[4][2];
#pragma unroll
    for (int h = 0; h < 4; h++) {
        mh[h][0] = g_m[(4 + h) * NTOK + r0i];
        mh[h][1] = g_m[(4 + h) * NTOK + r1i];
        iv[h][0] = g_invl[(4 + h) * NTOK + r0i];
        iv[h][1] = g_invl[(4 + h) * NTOK + r1i];
    }

    float facc[8][4];
#pragma unroll
    for (int ni = 0; ni < 8; ni++)
#pragma unroll
        for (int c = 0; c < 4; c++) facc[ni][c] = 0.f;

    for (int h = 0; h < 4; h++) {
        __syncthreads();
#pragma unroll
        for (int it = 0; it < 8; it++) {
            int idx = it * 256 + tid;
            int r = idx >> 4, c = (idx & 15) * 4;
            float4 v = *(const float4*)&buf[(size_t)(q0 + r) * QKV + h * 64 + c];
            Qs[r * 68 + c + 0] = f2tf(v.x); Qs[r * 68 + c + 1] = f2tf(v.y);
            Qs[r * 68 + c + 2] = f2tf(v.z); Qs[r * 68 + c + 3] = f2tf(v.w);
        }
#pragma unroll
        for (int it = 0; it < 4; it++) {
            int idx = it * 256 + tid;
            int r = idx >> 4, c = (idx & 15) * 4;
            int srow = selS[r];
            int rr = srow < 0 ? 0 : srow;
            float4 u = *(const float4*)&buf[(size_t)rr * QKV + 256 + h * 64 + c];
            Ks[r * 68 + c + 0] = f2tf(u.x); Ks[r * 68 + c + 1] = f2tf(u.y);
            Ks[r * 68 + c + 2] = f2tf(u.z); Ks[r * 68 + c + 3] = f2tf(u.w);
        }
        __syncthreads();

        float sacc[8][4];
#pragma unroll
        for (int ni = 0; ni < 8; ni++)
#pragma unroll
            for (int c = 0; c < 4; c++) sacc[ni][c] = 0.f;
#pragma unroll
        for (int ks = 0; ks < 8; ks++) {
            int kl = ks * 8;
            unsigned a0 = Qs[rb * 68 + kl + t];
            unsigned a1 = Qs[(rb + 8) * 68 + kl + t];
            unsigned a2 = Qs[rb * 68 + kl + t + 4];
            unsigned a3 = Qs[(rb + 8) * 68 + kl + t + 4];
#pragma unroll
            for (int ni = 0; ni < 8; ni++) {
                unsigned b0 = Ks[(ni * 8 + g) * 68 + kl + t];
                unsigned b1 = Ks[(ni * 8 + g) * 68 + kl + t + 4];
                mma8(sacc[ni][0], sacc[ni][1], sacc[ni][2], sacc[ni][3],
                     a0, a1, a2, a3, b0, b1);
            }
        }
#pragma unroll
        for (int ni = 0; ni < 8; ni++) {
            facc[ni][0] += __expf(sacc[ni][0] * 0.125f - mh[h][0]) * iv[h][0];
            facc[ni][1] += __expf(sacc[ni][1] * 0.125f - mh[h][0]) * iv[h][0];
            facc[ni][2] += __expf(sacc[ni][2] * 0.125f - mh[h][1]) * iv[h][1];
            facc[ni][3] += __expf(sacc[ni][3] * 0.125f - mh[h][1]) * iv[h][1];
        }
    }
    float* arow0 = attn + ((size_t)(NTOK + r0i)) * NTOK;
    float* arow1 = attn + ((size_t)(NTOK + r1i)) * NTOK;
#pragma unroll
    for (int ni = 0; ni < 8; ni++) {
        int c0 = ni * 8 + 2 * t;
        int s0 = selS[c0], s1 = selS[c0 + 1];
        if (s0 >= 0) {
            arow0[s0] = facc[ni][0] * 0.25f;
            arow1[s0] = facc[ni][2] * 0.25f;
        }
        if (s1 >= 0) {
            arow0[s1] = facc[ni][1] * 0.25f;
            arow1[s1] = facc[ni][3] * 0.25f;
        }
    }
}

// ---------------- zero-fill content attn half ---------------------------------
__global__ __launch_bounds__(256) void fill_zero(float* __restrict__ p)
{
    size_t base = ((size_t)blockIdx.x * 256 + threadIdx.x) * 16;
    float4 z = make_float4(0.f, 0.f, 0.f, 0.f);
#pragma unroll
    for (int i = 0; i < 4; i++)
        *(float4*)&p[base + i * 4] = z;
}

// ---------------- fp32 tiled GEMM (saliency s1, exact) ------------------------
__global__ __launch_bounds__(256) void gemm_kernel(
    const float* __restrict__ A, const float* __restrict__ W,
    const float* __restrict__ bias, float* __restrict__ C,
    int M, int Nc, int K, int gelu_flag, int accum)
{
    __shared__ float As[64][68];
    __shared__ float Ws2[64][68];
    int tx = threadIdx.x & 15, ty = threadIdx.x >> 4;
    int n0 = blockIdx.x * 64, m0 = blockIdx.y * 64;
    float acc[4][4];
#pragma unroll
    for (int i = 0; i < 4; i++)
#pragma unroll
        for (int j = 0; j < 4; j++) acc[i][j] = 0.f;

    for (int k0 = 0; k0 < K; k0 += 64) {
        for (int t = threadIdx.x; t < 4096; t += 256) {
            int m = t >> 6, k = t & 63;
            As[k][m] = A[(size_t)(m0 + m) * K + k0 + k];
        }
        for (int t = threadIdx.x; t < 4096; t += 256) {
            int k = t >> 6, n = t & 63;
            Ws2[k][n] = W[(size_t)(k0 + k) * Nc + n0 + n];
        }
        __syncthreads();
#pragma unroll 16
        for (int kk = 0; kk < 64; kk++) {
            float4 a4 = *(const float4*)&As[kk][ty * 4];
            float4 b4 = *(const float4*)&Ws2[kk][tx * 4];
            float a[4] = {a4.x, a4.y, a4.z, a4.w};
            float b[4] = {b4.x, b4.y, b4.z, b4.w};
#pragma unroll
            for (int i = 0; i < 4; i++)
#pragma unroll
                for (int j = 0; j < 4; j++) acc[i][j] += a[i] * b[j];
        }
        __syncthreads();
    }
#pragma unroll
    for (int i = 0; i < 4; i++) {
        int m = m0 + ty * 4 + i;
        float* crow = C + (size_t)m * Nc + n0 + tx * 4;
        float v[4];
#pragma unroll
        for (int j = 0; j < 4; j++) {
            float c = acc[i][j] + bias[n0 + tx * 4 + j];
            if (gelu_flag)
                c = 0.5f * c * (1.0f + erff(c * 0.70710678118654752f));
            v[j] = c;
        }
        if (accum) {
            float4 prev = *(const float4*)crow;
            v[0] += prev.x; v[1] += prev.y; v[2] += prev.z; v[3] += prev.w;
        }
        *(float4*)crow = make_float4(v[0], v[1], v[2], v[3]);
    }
}

// ---------------- saliency scores + exact top-k mask + compaction -------------
__global__ __launch_bounds__(256) void scores_kernel(
    const float* __restrict__ Ws2, const float* __restrict__ bs2)
{
    int t = blockIdx.x * 8 + (threadIdx.x >> 5);
    int lane = threadIdx.x & 31;
    const float* hp = g_h + (size_t)t * 256;
    float s = 0.f;
    for (int i = lane; i < 256; i += 32) s += hp[i] * Ws2[i];
#pragma unroll
    for (int off = 16; off; off >>= 1) s += __shfl_xor_sync(0xffffffffu, s, off);
    if (lane == 0) g_scores[t] = s + bs2[0];
}

__global__ __launch_bounds__(256) void mask_kernel()
{
    __shared__ float sc[NTOK];
    for (int i = threadIdx.x; i < NTOK; i += 256) sc[i] = g_scores[i];
    __syncthreads();
    int i = blockIdx.x * 256 + threadIdx.x;
    float si = sc[i];
    int cnt = 0;
    for (int j = 0; j < NTOK; j++) {
        float sj = sc[j];
        cnt += (sj > si) || (sj == si && j < i);
    }
    g_mask[i] = (cnt < KSEL) ? 1 : 0;
}

// deterministic compaction: single block, 1024-thread prefix scan
__global__ __launch_bounds__(1024) void compact_kernel()
{
    __shared__ int pre[1024];
    int tid = threadIdx.x;
    int base = tid * 4;
    int m0 = g_mask[base], m1 = g_mask[base + 1];
    int m2 = g_mask[base + 2], m3 = g_mask[base + 3];
    int s = m0 + m1 + m2 + m3;
    pre[tid] = s;
    __syncthreads();
    for (int off = 1; off < 1024; off <<= 1) {
        int v = (tid >= off) ? pre[tid - off] : 0;
        __syncthreads();
        pre[tid] += v;
        __syncthreads();
    }
    int p = pre[tid] - s;
    if (m0) g_sel[p++] = base;
    if (m1) g_sel[p++] = base + 1;
    if (m2) g_sel[p++] = base + 2;
    if (m3) g_sel[p++] = base + 3;
    if (tid < SELPAD - KSEL) g_sel[KSEL + tid] = -1;
}

// -----------------------------------------------------------------------------
extern "C" void kernel_launch(void* const* d_in, const int* in_sizes, int n_in,
                              void* d_out, int out_size)
{
    const float* x       = (const float*)d_in[0];
    const float* W_lqkv  = (const float*)d_in[1];
    const float* b_lqkv  = (const float*)d_in[2];
    const float* W_cqkv  = (const float*)d_in[3];
    const float* b_cqkv  = (const float*)d_in[4];
    const float* W_lproj = (const float*)d_in[5];
    const float* b_lproj = (const float*)d_in[6];
    const float* W_cproj = (const float*)d_in[7];
    const float* b_cproj = (const float*)d_in[8];
    const float* W_s1    = (const float*)d_in[9];
    const float* b_s1    = (const float*)d_in[10];
    const float* W_s2    = (const float*)d_in[11];
    const float* b_s2    = (const float*)d_in[12];

    float* out  = (float*)d_out;
    float* attn = out + (size_t)NTOK * DDIM;

    float *p_lqkv, *p_cqkv, *p_h, *p_o;
    cudaGetSymbolAddress((void**)&p_lqkv, g_lqkv);
    cudaGetSymbolAddress((void**)&p_cqkv, g_cqkv);
    cudaGetSymbolAddress((void**)&p_h,    g_h);
    cudaGetSymbolAddress((void**)&p_o,    g_o);

    static int attr_done = 0;
    if (!attr_done) {
        cudaFuncSetAttribute(flash_kernel,
            cudaFuncAttributeMaxDynamicSharedMemorySize, FLASH_SMEM);
        cudaFuncSetAttribute(attn_local,
            cudaFuncAttributeMaxDynamicSharedMemorySize, ATTNL_SMEM);
        cudaFuncSetAttribute(attn_content,
            cudaFuncAttributeMaxDynamicSharedMemorySize, ATTNC_SMEM);
        attr_done = 1;
    }

    // QKV projections (tf32 tensor cores)
    proj_tf32<<<dim3(12, 32), 128>>>(x, W_lqkv, b_lqkv, p_lqkv, QKV, DDIM, 0);
    proj_tf32<<<dim3(12, 32), 128>>>(x, W_cqkv, b_cqkv, p_cqkv, QKV, DDIM, 0);

    // saliency path (exact fp32 — guards the top-k boundary)
    gemm_kernel<<<dim3(4, 64), 256>>>(x, W_s1, b_s1, p_h, NTOK, 256, DDIM, 1, 0);
    scores_kernel<<<512, 256>>>(W_s2, b_s2);
    mask_kernel<<<16, 256>>>();
    compact_kernel<<<1, 1024>>>();

    // zero-fill content attn half (overwritten at selected columns below)
    fill_zero<<<4096, 256>>>(attn + (size_t)NTOK * NTOK);

    // attention core (flash; content heads use compacted key list)
    flash_kernel<<<dim3(32, 8), 256, FLASH_SMEM>>>();

    // attn output halves
    attn_local<<<dim3(32, 32), 256, ATTNL_SMEM>>>(attn);
    attn_content<<<dim3(NCHUNK_C, 32), 256, ATTNC_SMEM>>>(attn);

    // output projections (tf32, accumulate branches)
    proj_tf32<<<dim3(8, 32), 128>>>(p_o,              W_lproj, b_lproj, out, DDIM, 256, 0);
    proj_tf32<<<dim3(8, 32), 128>>>(p_o + NTOK * 256, W_cproj, b_cproj, out, DDIM, 256, 1);
}

// round 7
// speedup vs baseline: 3.3005x; 1.0273x over previous
#include <cuda_runtime.h>
#include <math.h>

#define NTOK 4096
#define DDIM 512
#define QKV  768
#define KSEL 819
#define SELPAD 832          // KSEL padded to multiple of 64
#define NCHUNK_C 13         // SELPAD / 64

// ---------------- scratch (device globals; no runtime allocation) -------------
__device__ float g_lqkv[NTOK * QKV];
__device__ float g_cqkv[NTOK * QKV];
__device__ float g_h[NTOK * 256];
__device__ float g_scores[NTOK];
__device__ int   g_mask[NTOK];
__device__ int   g_sel[SELPAD];
__device__ float g_m[8 * NTOK];
__device__ float g_invl[8 * NTOK];
__device__ float g_o[2 * NTOK * 256];

// ---------------- tf32 helpers ------------------------------------------------
__device__ __forceinline__ unsigned f2tf(float f) {
    unsigned r;
    asm("cvt.rna.tf32.f32 %0, %1;" : "=r"(r) : "f"(f));
    return r;
}
__device__ __forceinline__ void mma8(float& c0, float& c1, float& c2, float& c3,
                                     unsigned a0, unsigned a1, unsigned a2, unsigned a3,
                                     unsigned b0, unsigned b1)
{
    asm volatile(
        "mma.sync.aligned.m16n8k8.row.col.f32.tf32.tf32.f32 "
        "{%0,%1,%2,%3},{%4,%5,%6,%7},{%8,%9},{%0,%1,%2,%3};"
        : "+f"(c0), "+f"(c1), "+f"(c2), "+f"(c3)
        : "r"(a0), "r"(a1), "r"(a2), "r"(a3), "r"(b0), "r"(b1));
}

// ---------------- tf32 GEMM: C = A@W + bias (opt accumulate into C) -----------
__global__ __launch_bounds__(128) void proj_tf32(
    const float* __restrict__ A, const float* __restrict__ W,
    const float* __restrict__ bias, float* __restrict__ C, int Nc, int K,
    int accum)
{
    __shared__ unsigned Xs[128][36];
    __shared__ unsigned Ws[32][72];
    int t = threadIdx.x & 3, g = (threadIdx.x >> 2) & 7, w = threadIdx.x >> 5;
    int m0 = blockIdx.y * 128, n0 = blockIdx.x * 64;

    float acc[2][8][4];
#pragma unroll
    for (int mi = 0; mi < 2; mi++)
#pragma unroll
        for (int ni = 0; ni < 8; ni++)
#pragma unroll
            for (int c = 0; c < 4; c++) acc[mi][ni][c] = 0.f;

    for (int k0 = 0; k0 < K; k0 += 32) {
#pragma unroll
        for (int it = 0; it < 8; it++) {
            int idx = it * 128 + threadIdx.x;
            int row = idx >> 3, c4 = (idx & 7) * 4;
            float4 v = *(const float4*)&A[(size_t)(m0 + row) * K + k0 + c4];
            Xs[row][c4 + 0] = f2tf(v.x); Xs[row][c4 + 1] = f2tf(v.y);
            Xs[row][c4 + 2] = f2tf(v.z); Xs[row][c4 + 3] = f2tf(v.w);
        }
#pragma unroll
        for (int it = 0; it < 4; it++) {
            int idx = it * 128 + threadIdx.x;
            int kr = idx >> 4, n4 = (idx & 15) * 4;
            float4 v = *(const float4*)&W[(size_t)(k0 + kr) * Nc + n0 + n4];
            Ws[kr][n4 + 0] = f2tf(v.x); Ws[kr][n4 + 1] = f2tf(v.y);
            Ws[kr][n4 + 2] = f2tf(v.z); Ws[kr][n4 + 3] = f2tf(v.w);
        }
        __syncthreads();
#pragma unroll
        for (int ks = 0; ks < 4; ks++) {
            int kl = ks * 8;
            unsigned a[2][4];
#pragma unroll
            for (int mi = 0; mi < 2; mi++) {
                int r = w * 32 + mi * 16 + g;
                a[mi][0] = Xs[r][kl + t];      a[mi][1] = Xs[r + 8][kl + t];
                a[mi][2] = Xs[r][kl + t + 4];  a[mi][3] = Xs[r + 8][kl + t + 4];
            }
#pragma unroll
            for (int ni = 0; ni < 8; ni++) {
                unsigned b0 = Ws[kl + t][ni * 8 + g];
                unsigned b1 = Ws[kl + t + 4][ni * 8 + g];
#pragma unroll
                for (int mi = 0; mi < 2; mi++)
                    mma8(acc[mi][ni][0], acc[mi][ni][1], acc[mi][ni][2], acc[mi][ni][3],
                         a[mi][0], a[mi][1], a[mi][2], a[mi][3], b0, b1);
            }
        }
        __syncthreads();
    }
#pragma unroll
    for (int mi = 0; mi < 2; mi++)
#pragma unroll
        for (int ni = 0; ni < 8; ni++) {
            int m = m0 + w * 32 + mi * 16 + g;
            int n = n0 + ni * 8 + 2 * t;
            float bv0 = bias[n], bv1 = bias[n + 1];
            float v00 = acc[mi][ni][0] + bv0, v01 = acc[mi][ni][1] + bv1;
            float v10 = acc[mi][ni][2] + bv0, v11 = acc[mi][ni][3] + bv1;
            float* p0 = &C[(size_t)m * Nc + n];
            float* p1 = &C[(size_t)(m + 8) * Nc + n];
            if (accum) {
                float2 q0 = *(const float2*)p0, q1 = *(const float2*)p1;
                v00 += q0.x; v01 += q0.y; v10 += q1.x; v11 += q1.y;
            }
            *(float2*)p0 = make_float2(v00, v01);
            *(float2*)p1 = make_float2(v10, v11);
        }
}

// ---------------- 3xTF32 error-compensated GEMM + exact GELU (saliency s1) ----
// h = gelu(x @ W_s1 + b); fp32-equivalent accuracy via hi/lo split
// block tile 64m x 64n, k-chunk 32; 4 warps, warp tile 16m x 64n
__global__ __launch_bounds__(128) void s1_tf32x3(
    const float* __restrict__ A, const float* __restrict__ W,
    const float* __restrict__ bias, float* __restrict__ C, int Nc, int K)
{
    __shared__ unsigned Xhi[64][36], Xlo[64][36];
    __shared__ unsigned Whi[32][72], Wlo[32][72];
    int t = threadIdx.x & 3, g = (threadIdx.x >> 2) & 7, w = threadIdx.x >> 5;
    int m0 = blockIdx.y * 64, n0 = blockIdx.x * 64;

    float acc[8][4];
#pragma unroll
    for (int ni = 0; ni < 8; ni++)
#pragma unroll
        for (int c = 0; c < 4; c++) acc[ni][c] = 0.f;

    for (int k0 = 0; k0 < K; k0 += 32) {
#pragma unroll
        for (int it = 0; it < 4; it++) {
            int idx = it * 128 + threadIdx.x;
            int row = idx >> 3, c4 = (idx & 7) * 4;
            float4 v = *(const float4*)&A[(size_t)(m0 + row) * K + k0 + c4];
            float vv[4] = {v.x, v.y, v.z, v.w};
#pragma unroll
            for (int j = 0; j < 4; j++) {
                unsigned hi = f2tf(vv[j]);
                Xhi[row][c4 + j] = hi;
                Xlo[row][c4 + j] = f2tf(vv[j] - __uint_as_float(hi));
            }
        }
#pragma unroll
        for (int it = 0; it < 4; it++) {
            int idx = it * 128 + threadIdx.x;
            int kr = idx >> 4, n4 = (idx & 15) * 4;
            float4 v = *(const float4*)&W[(size_t)(k0 + kr) * Nc + n0 + n4];
            float vv[4] = {v.x, v.y, v.z, v.w};
#pragma unroll
            for (int j = 0; j < 4; j++) {
                unsigned hi = f2tf(vv[j]);
                Whi[kr][n4 + j] = hi;
                Wlo[kr][n4 + j] = f2tf(vv[j] - __uint_as_float(hi));
            }
        }
        __syncthreads();
#pragma unroll
        for (int ks = 0; ks < 4; ks++) {
            int kl = ks * 8;
            int r = w * 16 + g;
            unsigned ah[4], al[4];
            ah[0] = Xhi[r][kl + t];      ah[1] = Xhi[r + 8][kl + t];
            ah[2] = Xhi[r][kl + t + 4];  ah[3] = Xhi[r + 8][kl + t + 4];
            al[0] = Xlo[r][kl + t];      al[1] = Xlo[r + 8][kl + t];
            al[2] = Xlo[r][kl + t + 4];  al[3] = Xlo[r + 8][kl + t + 4];
#pragma unroll
            for (int ni = 0; ni < 8; ni++) {
                unsigned bh0 = Whi[kl + t][ni * 8 + g];
                unsigned bh1 = Whi[kl + t + 4][ni * 8 + g];
                unsigned bl0 = Wlo[kl + t][ni * 8 + g];
                unsigned bl1 = Wlo[kl + t + 4][ni * 8 + g];
                mma8(acc[ni][0], acc[ni][1], acc[ni][2], acc[ni][3],
                     al[0], al[1], al[2], al[3], bh0, bh1);
                mma8(acc[ni][0], acc[ni][1], acc[ni][2], acc[ni][3],
                     ah[0], ah[1], ah[2], ah[3], bl0, bl1);
                mma8(acc[ni][0], acc[ni][1], acc[ni][2], acc[ni][3],
                     ah[0], ah[1], ah[2], ah[3], bh0, bh1);
            }
        }
        __syncthreads();
    }
#pragma unroll
    for (int ni = 0; ni < 8; ni++) {
        int m = m0 + w * 16 + g;
        int n = n0 + ni * 8 + 2 * t;
        float bv0 = bias[n], bv1 = bias[n + 1];
        float vv[4] = {acc[ni][0] + bv0, acc[ni][1] + bv1,
                       acc[ni][2] + bv0, acc[ni][3] + bv1};
#pragma unroll
        for (int j = 0; j < 4; j++)
            vv[j] = 0.5f * vv[j] * (1.0f + erff(vv[j] * 0.70710678118654752f));
        *(float2*)&C[(size_t)m * Nc + n] = make_float2(vv[0], vv[1]);
        *(float2*)&C[(size_t)(m + 8) * Nc + n] = make_float2(vv[2], vv[3]);
    }
}

// ---------------- flash attention (no P smem round-trip; shfl transpose) ------
#define FLASH_SMEM ((128*68 + 64*68 + 64*72 + 64) * 4)
__global__ __launch_bounds__(256, 2) void flash_kernel()
{
    extern __shared__ unsigned sm[];
    unsigned* Qs = sm;                 // [128][68]
    unsigned* Ks = Qs + 128 * 68;      // [64][68]
    unsigned* Vs = Ks + 64 * 68;       // [64][72]
    int* maskCh  = (int*)(Vs + 64 * 72);   // [64]

    int hb = blockIdx.y;
    const float* buf = (hb < 4) ? g_lqkv : g_cqkv;
    int h = hb & 3;
    bool content = hb >= 4;
    int q0 = blockIdx.x * 128;
    int tid = threadIdx.x, lane = tid & 31, w = tid >> 5;
    int t = lane & 3, g = lane >> 2;
    int rb = w * 16 + g;
    int srcA = (g << 2) | (t >> 1);    // lane in same row-group holding cols 2t',2t'+1
    int srcB = srcA + 2;
    bool oddt = (t & 1);

#pragma unroll
    for (int it = 0; it < 8; it++) {
        int idx = it * 256 + tid;
        int r = idx >> 4, c = (idx & 15) * 4;
        float4 v = *(const float4*)&buf[(size_t)(q0 + r) * QKV + h * 64 + c];
        Qs[r * 68 + c + 0] = f2tf(v.x); Qs[r * 68 + c + 1] = f2tf(v.y);
        Qs[r * 68 + c + 2] = f2tf(v.z); Qs[r * 68 + c + 3] = f2tf(v.w);
    }

    float m0 = -1e30f, m1 = -1e30f, l0 = 0.f, l1 = 0.f;
    float oacc[8][4];
#pragma unroll
    for (int ni = 0; ni < 8; ni++)
#pragma unroll
        for (int c = 0; c < 4; c++) oacc[ni][c] = 0.f;

    int nch = content ? NCHUNK_C : (NTOK / 64);
    for (int ch = 0; ch < nch; ch++) {
        int kc = ch * 64;
        __syncthreads();
#pragma unroll
        for (int it = 0; it < 4; it++) {
            int idx = it * 256 + tid;
            int r = idx >> 4, c = (idx & 15) * 4;
            int srow = content ? g_sel[kc + r] : (kc + r);
            int rr = srow < 0 ? 0 : srow;
            float4 kv = *(const float4*)&buf[(size_t)rr * QKV + 256 + h * 64 + c];
            Ks[r * 68 + c + 0] = f2tf(kv.x); Ks[r * 68 + c + 1] = f2tf(kv.y);
            Ks[r * 68 + c + 2] = f2tf(kv.z); Ks[r * 68 + c + 3] = f2tf(kv.w);
            float4 vv = *(const float4*)&buf[(size_t)rr * QKV + 512 + h * 64 + c];
            Vs[r * 72 + c + 0] = f2tf(vv.x); Vs[r * 72 + c + 1] = f2tf(vv.y);
            Vs[r * 72 + c + 2] = f2tf(vv.z); Vs[r * 72 + c + 3] = f2tf(vv.w);
        }
        if (tid < 64) maskCh[tid] = content ? (g_sel[kc + tid] >= 0) : 1;
        __syncthreads();

        float sacc[8][4];
#pragma unroll
        for (int ni = 0; ni < 8; ni++)
#pragma unroll
            for (int c = 0; c < 4; c++) sacc[ni][c] = 0.f;
#pragma unroll
        for (int ks = 0; ks < 8; ks++) {
            int kl = ks * 8;
            unsigned a0 = Qs[rb * 68 + kl + t];
            unsigned a1 = Qs[(rb + 8) * 68 + kl + t];
            unsigned a2 = Qs[rb * 68 + kl + t + 4];
            unsigned a3 = Qs[(rb + 8) * 68 + kl + t + 4];
#pragma unroll
            for (int ni = 0; ni < 8; ni++) {
                unsigned b0 = Ks[(ni * 8 + g) * 68 + kl + t];
                unsigned b1 = Ks[(ni * 8 + g) * 68 + kl + t + 4];
                mma8(sacc[ni][0], sacc[ni][1], sacc[ni][2], sacc[ni][3],
                     a0, a1, a2, a3, b0, b1);
            }
        }
        float cm0 = -1e30f, cm1 = -1e30f;
#pragma unroll
        for (int ni = 0; ni < 8; ni++) {
            int c0 = ni * 8 + 2 * t;
            bool on0 = maskCh[c0];
            bool on1 = maskCh[c0 + 1];
            sacc[ni][0] *= 0.125f; sacc[ni][1] *= 0.125f;
            sacc[ni][2] *= 0.125f; sacc[ni][3] *= 0.125f;
            cm0 = fmaxf(cm0, fmaxf(on0 ? sacc[ni][0] : -1e30f, on1 ? sacc[ni][1] : -1e30f));
            cm1 = fmaxf(cm1, fmaxf(on0 ? sacc[ni][2] : -1e30f, on1 ? sacc[ni][3] : -1e30f));
        }
        cm0 = fmaxf(cm0, __shfl_xor_sync(0xffffffffu, cm0, 1));
        cm0 = fmaxf(cm0, __shfl_xor_sync(0xffffffffu, cm0, 2));
        cm1 = fmaxf(cm1, __shfl_xor_sync(0xffffffffu, cm1, 1));
        cm1 = fmaxf(cm1, __shfl_xor_sync(0xffffffffu, cm1, 2));

        float mn0 = fmaxf(m0, cm0), mn1 = fmaxf(m1, cm1);
        float r0 = __expf(m0 - mn0), r1 = __expf(m1 - mn1);
        m0 = mn0; m1 = mn1;

        float es0 = 0.f, es1 = 0.f;
#pragma unroll
        for (int ni = 0; ni < 8; ni++) {
            int c0 = ni * 8 + 2 * t;
            bool on0 = maskCh[c0];
            bool on1 = maskCh[c0 + 1];
            float e00 = on0 ? __expf(sacc[ni][0] - mn0) : 0.f;
            float e01 = on1 ? __expf(sacc[ni][1] - mn0) : 0.f;
            float e10 = on0 ? __expf(sacc[ni][2] - mn1) : 0.f;
            float e11 = on1 ? __expf(sacc[ni][3] - mn1) : 0.f;
            es0 += e00 + e01; es1 += e10 + e11;
            sacc[ni][0] = e00; sacc[ni][1] = e01;
            sacc[ni][2] = e10; sacc[ni][3] = e11;
        }
        es0 += __shfl_xor_sync(0xffffffffu, es0, 1);
        es0 += __shfl_xor_sync(0xffffffffu, es0, 2);
        es1 += __shfl_xor_sync(0xffffffffu, es1, 1);
        es1 += __shfl_xor_sync(0xffffffffu, es1, 2);
        l0 = l0 * r0 + es0;
        l1 = l1 * r1 + es1;
#pragma unroll
        for (int ni = 0; ni < 8; ni++) {
            oacc[ni][0] *= r0; oacc[ni][1] *= r0;
            oacc[ni][2] *= r1; oacc[ni][3] *= r1;
        }

        // PV: a-fragments built from sacc via in-warp transpose (C-layout -> A-layout)
#pragma unroll
        for (int ks = 0; ks < 8; ks++) {
            float v00 = __shfl_sync(0xffffffffu, sacc[ks][0], srcA);
            float v01 = __shfl_sync(0xffffffffu, sacc[ks][1], srcA);
            float v10 = __shfl_sync(0xffffffffu, sacc[ks][2], srcA);
            float v11 = __shfl_sync(0xffffffffu, sacc[ks][3], srcA);
            float w00 = __shfl_sync(0xffffffffu, sacc[ks][0], srcB);
            float w01 = __shfl_sync(0xffffffffu, sacc[ks][1], srcB);
            float w10 = __shfl_sync(0xffffffffu, sacc[ks][2], srcB);
            float w11 = __shfl_sync(0xffffffffu, sacc[ks][3], srcB);
            unsigned a0 = f2tf(oddt ? v01 : v00);   // P[rb][kl+t]
            unsigned a1 = f2tf(oddt ? v11 : v10);   // P[rb+8][kl+t]
            unsigned a2 = f2tf(oddt ? w01 : w00);   // P[rb][kl+t+4]
            unsigned a3 = f2tf(oddt ? w11 : w10);   // P[rb+8][kl+t+4]
            int kl = ks * 8;
#pragma unroll
            for (int ni = 0; ni < 8; ni++) {
                unsigned b0 = Vs[(kl + t) * 72 + ni * 8 + g];
                unsigned b1 = Vs[(kl + t + 4) * 72 + ni * 8 + g];
                mma8(oacc[ni][0], oacc[ni][1], oacc[ni][2], oacc[ni][3],
                     a0, a1, a2, a3, b0, b1);
            }
        }
    }

    float iv0 = 1.0f / l0, iv1 = 1.0f / l1;
    int bB = hb >> 2;
    size_t ob = (size_t)bB * NTOK * 256;
    int r0i = q0 + rb, r1i = r0i + 8;
#pragma unroll
    for (int ni = 0; ni < 8; ni++) {
        int d = h * 64 + ni * 8 + 2 * t;
        *(float2*)&g_o[ob + (size_t)r0i * 256 + d] =
            make_float2(oacc[ni][0] * iv0, oacc[ni][1] * iv0);
        *(float2*)&g_o[ob + (size_t)r1i * 256 + d] =
            make_float2(oacc[ni][2] * iv1, oacc[ni][3] * iv1);
    }
    if (t == 0) {
        g_invl[hb * NTOK + r0i] = iv0; g_invl[hb * NTOK + r1i] = iv1;
        g_m[hb * NTOK + r0i] = m0;     g_m[hb * NTOK + r1i] = m1;
    }
}

// ---------------- attn local half: dense recompute + head-mean ----------------
#define ATTNL_SMEM ((128*68 + 128*68) * 4)
__global__ __launch_bounds__(256) void attn_local(float* __restrict__ attn)
{
    extern __shared__ unsigned sm[];
    unsigned* Qs = sm;                 // [128][68]
    unsigned* Ks = Qs + 128 * 68;      // [128][68]

    const float* buf = g_lqkv;
    int q0 = blockIdx.y * 128, k0 = blockIdx.x * 128;
    int tid = threadIdx.x, lane = tid & 31, w = tid >> 5;
    int t = lane & 3, g = lane >> 2;
    int rb = w * 16 + g;
    int r0i = q0 + rb, r1i = r0i + 8;

    float mh[4][2], iv[4][2];
#pragma unroll
    for (int h = 0; h < 4; h++) {
        mh[h][0] = g_m[h * NTOK + r0i];
        mh[h][1] = g_m[h * NTOK + r1i];
        iv[h][0] = g_invl[h * NTOK + r0i];
        iv[h][1] = g_invl[h * NTOK + r1i];
    }

    float facc[16][4];
#pragma unroll
    for (int ni = 0; ni < 16; ni++)
#pragma unroll
        for (int c = 0; c < 4; c++) facc[ni][c] = 0.f;

    for (int h = 0; h < 4; h++) {
        __syncthreads();
#pragma unroll
        for (int it = 0; it < 8; it++) {
            int idx = it * 256 + tid;
            int r = idx >> 4, c = (idx & 15) * 4;
            float4 v = *(const float4*)&buf[(size_t)(q0 + r) * QKV + h * 64 + c];
            Qs[r * 68 + c + 0] = f2tf(v.x); Qs[r * 68 + c + 1] = f2tf(v.y);
            Qs[r * 68 + c + 2] = f2tf(v.z); Qs[r * 68 + c + 3] = f2tf(v.w);
            float4 u = *(const float4*)&buf[(size_t)(k0 + r) * QKV + 256 + h * 64 + c];
            Ks[r * 68 + c + 0] = f2tf(u.x); Ks[r * 68 + c + 1] = f2tf(u.y);
            Ks[r * 68 + c + 2] = f2tf(u.z); Ks[r * 68 + c + 3] = f2tf(u.w);
        }
        __syncthreads();

        float sacc[16][4];
#pragma unroll
        for (int ni = 0; ni < 16; ni++)
#pragma unroll
            for (int c = 0; c < 4; c++) sacc[ni][c] = 0.f;
#pragma unroll
        for (int ks = 0; ks < 8; ks++) {
            int kl = ks * 8;
            unsigned a0 = Qs[rb * 68 + kl + t];
            unsigned a1 = Qs[(rb + 8) * 68 + kl + t];
            unsigned a2 = Qs[rb * 68 + kl + t + 4];
            unsigned a3 = Qs[(rb + 8) * 68 + kl + t + 4];
#pragma unroll
            for (int ni = 0; ni < 16; ni++) {
                unsigned b0 = Ks[(ni * 8 + g) * 68 + kl + t];
                unsigned b1 = Ks[(ni * 8 + g) * 68 + kl + t + 4];
                mma8(sacc[ni][0], sacc[ni][1], sacc[ni][2], sacc[ni][3],
                     a0, a1, a2, a3, b0, b1);
            }
        }
#pragma unroll
        for (int ni = 0; ni < 16; ni++) {
            facc[ni][0] += __expf(sacc[ni][0] * 0.125f - mh[h][0]) * iv[h][0];
            facc[ni][1] += __expf(sacc[ni][1] * 0.125f - mh[h][0]) * iv[h][0];
            facc[ni][2] += __expf(sacc[ni][2] * 0.125f - mh[h][1]) * iv[h][1];
            facc[ni][3] += __expf(sacc[ni][3] * 0.125f - mh[h][1]) * iv[h][1];
        }
    }
#pragma unroll
    for (int ni = 0; ni < 16; ni++) {
        int kk = k0 + ni * 8 + 2 * t;
        *(float2*)&attn[(size_t)r0i * NTOK + kk] =
            make_float2(facc[ni][0] * 0.25f, facc[ni][1] * 0.25f);
        *(float2*)&attn[(size_t)r1i * NTOK + kk] =
            make_float2(facc[ni][2] * 0.25f, facc[ni][3] * 0.25f);
    }
}

// ---------------- attn content half: only selected columns --------------------
#define ATTNC_SMEM ((128*68 + 64*68 + 64) * 4)
__global__ __launch_bounds__(256) void attn_content(float* __restrict__ attn)
{
    extern __shared__ unsigned sm[];
    unsigned* Qs = sm;                 // [128][68]
    unsigned* Ks = Qs + 128 * 68;      // [64][68]
    int* selS    = (int*)(Ks + 64 * 68);   // [64]

    const float* buf = g_cqkv;
    int q0 = blockIdx.y * 128;
    int k0s = blockIdx.x * 64;
    int tid = threadIdx.x, lane = tid & 31, w = tid >> 5;
    int t = lane & 3, g = lane >> 2;
    int rb = w * 16 + g;
    int r0i = q0 + rb, r1i = r0i + 8;

    if (tid < 64) selS[tid] = g_sel[k0s + tid];

    float mh[4][2], iv[4][2];
#pragma unroll
    for (int h = 0; h < 4; h++) {
        mh[h][0] = g_m[(4 + h) * NTOK + r0i];
        mh[h][1] = g_m[(4 + h) * NTOK + r1i];
        iv[h][0] = g_invl[(4 + h) * NTOK + r0i];
        iv[h][1] = g_invl[(4 + h) * NTOK + r1i];
    }

    float facc[8][4];
#pragma unroll
    for (int ni = 0; ni < 8; ni++)
#pragma unroll
        for (int c = 0; c < 4; c++) facc[ni][c] = 0.f;

    for (int h = 0; h < 4; h++) {
        __syncthreads();
#pragma unroll
        for (int it = 0; it < 8; it++) {
            int idx = it * 256 + tid;
            int r = idx >> 4, c = (idx & 15) * 4;
            float4 v = *(const float4*)&buf[(size_t)(q0 + r) * QKV + h * 64 + c];
            Qs[r * 68 + c + 0] = f2tf(v.x); Qs[r * 68 + c + 1] = f2tf(v.y);
            Qs[r * 68 + c + 2] = f2tf(v.z); Qs[r * 68 + c + 3] = f2tf(v.w);
        }
#pragma unroll
        for (int it = 0; it < 4; it++) {
            int idx = it * 256 + tid;
            int r = idx >> 4, c = (idx & 15) * 4;
            int srow = selS[r];
            int rr = srow < 0 ? 0 : srow;
            float4 u = *(const float4*)&buf[(size_t)rr * QKV + 256 + h * 64 + c];
            Ks[r * 68 + c + 0] = f2tf(u.x); Ks[r * 68 + c + 1] = f2tf(u.y);
            Ks[r * 68 + c + 2] = f2tf(u.z); Ks[r * 68 + c + 3] = f2tf(u.w);
        }
        __syncthreads();

        float sacc[8][4];
#pragma unroll
        for (int ni = 0; ni < 8; ni++)
#pragma unroll
            for (int c = 0; c < 4; c++) sacc[ni][c] = 0.f;
#pragma unroll
        for (int ks = 0; ks < 8; ks++) {
            int kl = ks * 8;
            unsigned a0 = Qs[rb * 68 + kl + t];
            unsigned a1 = Qs[(rb + 8) * 68 + kl + t];
            unsigned a2 = Qs[rb * 68 + kl + t + 4];
            unsigned a3 = Qs[(rb + 8) * 68 + kl + t + 4];
#pragma unroll
            for (int ni = 0; ni < 8; ni++) {
                unsigned b0 = Ks[(ni * 8 + g) * 68 + kl + t];
                unsigned b1 = Ks[(ni * 8 + g) * 68 + kl + t + 4];
                mma8(sacc[ni][0], sacc[ni][1], sacc[ni][2], sacc[ni][3],
                     a0, a1, a2, a3, b0, b1);
            }
        }
#pragma unroll
        for (int ni = 0; ni < 8; ni++) {
            facc[ni][0] += __expf(sacc[ni][0] * 0.125f - mh[h][0]) * iv[h][0];
            facc[ni][1] += __expf(sacc[ni][1] * 0.125f - mh[h][0]) * iv[h][0];
            facc[ni][2] += __expf(sacc[ni][2] * 0.125f - mh[h][1]) * iv[h][1];
            facc[ni][3] += __expf(sacc[ni][3] * 0.125f - mh[h][1]) * iv[h][1];
        }
    }
    float* arow0 = attn + ((size_t)(NTOK + r0i)) * NTOK;
    float* arow1 = attn + ((size_t)(NTOK + r1i)) * NTOK;
#pragma unroll
    for (int ni = 0; ni < 8; ni++) {
        int c0 = ni * 8 + 2 * t;
        int s0 = selS[c0], s1 = selS[c0 + 1];
        if (s0 >= 0) {
            arow0[s0] = facc[ni][0] * 0.25f;
            arow1[s0] = facc[ni][2] * 0.25f;
        }
        if (s1 >= 0) {
            arow0[s1] = facc[ni][1] * 0.25f;
            arow1[s1] = facc[ni][3] * 0.25f;
        }
    }
}

// ---------------- zero-fill content attn half ---------------------------------
__global__ __launch_bounds__(256) void fill_zero(float* __restrict__ p)
{
    size_t base = ((size_t)blockIdx.x * 256 + threadIdx.x) * 16;
    float4 z = make_float4(0.f, 0.f, 0.f, 0.f);
#pragma unroll
    for (int i = 0; i < 4; i++)
        *(float4*)&p[base + i * 4] = z;
}

// ---------------- saliency scores + exact top-k mask + compaction -------------
__global__ __launch_bounds__(256) void scores_kernel(
    const float* __restrict__ Ws2, const float* __restrict__ bs2)
{
    int t = blockIdx.x * 8 + (threadIdx.x >> 5);
    int lane = threadIdx.x & 31;
    const float* hp = g_h + (size_t)t * 256;
    float s = 0.f;
    for (int i = lane; i < 256; i += 32) s += hp[i] * Ws2[i];
#pragma unroll
    for (int off = 16; off; off >>= 1) s += __shfl_xor_sync(0xffffffffu, s, off);
    if (lane == 0) g_scores[t] = s + bs2[0];
}

__global__ __launch_bounds__(256) void mask_kernel()
{
    __shared__ float sc[NTOK];
    for (int i = threadIdx.x; i < NTOK; i += 256) sc[i] = g_scores[i];
    __syncthreads();
    int i = blockIdx.x * 256 + threadIdx.x;
    float si = sc[i];
    int cnt = 0;
    for (int j = 0; j < NTOK; j++) {
        float sj = sc[j];
        cnt += (sj > si) || (sj == si && j < i);
    }
    g_mask[i] = (cnt < KSEL) ? 1 : 0;
}

__global__ __launch_bounds__(1024) void compact_kernel()
{
    __shared__ int pre[1024];
    int tid = threadIdx.x;
    int base = tid * 4;
    int m0 = g_mask[base], m1 = g_mask[base + 1];
    int m2 = g_mask[base + 2], m3 = g_mask[base + 3];
    int s = m0 + m1 + m2 + m3;
    pre[tid] = s;
    __syncthreads();
    for (int off = 1; off < 1024; off <<= 1) {
        int v = (tid >= off) ? pre[tid - off] : 0;
        __syncthreads();
        pre[tid] += v;
        __syncthreads();
    }
    int p = pre[tid] - s;
    if (m0) g_sel[p++] = base;
    if (m1) g_sel[p++] = base + 1;
    if (m2) g_sel[p++] = base + 2;
    if (m3) g_sel[p++] = base + 3;
    if (tid < SELPAD - KSEL) g_sel[KSEL + tid] = -1;
}

// -----------------------------------------------------------------------------
extern "C" void kernel_launch(void* const* d_in, const int* in_sizes, int n_in,
                              void* d_out, int out_size)
{
    const float* x       = (const float*)d_in[0];
    const float* W_lqkv  = (const float*)d_in[1];
    const float* b_lqkv  = (const float*)d_in[2];
    const float* W_cqkv  = (const float*)d_in[3];
    const float* b_cqkv  = (const float*)d_in[4];
    const float* W_lproj = (const float*)d_in[5];
    const float* b_lproj = (const float*)d_in[6];
    const float* W_cproj = (const float*)d_in[7];
    const float* b_cproj = (const float*)d_in[8];
    const float* W_s1    = (const float*)d_in[9];
    const float* b_s1    = (const float*)d_in[10];
    const float* W_s2    = (const float*)d_in[11];
    const float* b_s2    = (const float*)d_in[12];

    float* out  = (float*)d_out;
    float* attn = out + (size_t)NTOK * DDIM;

    float *p_lqkv, *p_cqkv, *p_h, *p_o;
    cudaGetSymbolAddress((void**)&p_lqkv, g_lqkv);
    cudaGetSymbolAddress((void**)&p_cqkv, g_cqkv);
    cudaGetSymbolAddress((void**)&p_h,    g_h);
    cudaGetSymbolAddress((void**)&p_o,    g_o);

    static int attr_done = 0;
    if (!attr_done) {
        cudaFuncSetAttribute(flash_kernel,
            cudaFuncAttributeMaxDynamicSharedMemorySize, FLASH_SMEM);
        cudaFuncSetAttribute(attn_local,
            cudaFuncAttributeMaxDynamicSharedMemorySize, ATTNL_SMEM);
        cudaFuncSetAttribute(attn_content,
            cudaFuncAttributeMaxDynamicSharedMemorySize, ATTNC_SMEM);
        attr_done = 1;
    }

    // QKV projections (tf32 tensor cores)
    proj_tf32<<<dim3(12, 32), 128>>>(x, W_lqkv, b_lqkv, p_lqkv, QKV, DDIM, 0);
    proj_tf32<<<dim3(12, 32), 128>>>(x, W_cqkv, b_cqkv, p_cqkv, QKV, DDIM, 0);

    // saliency path (3xTF32 — fp32-equivalent accuracy, protects top-k boundary)
    s1_tf32x3<<<dim3(4, 64), 128>>>(x, W_s1, b_s1, p_h, 256, DDIM);
    scores_kernel<<<512, 256>>>(W_s2, b_s2);
    mask_kernel<<<16, 256>>>();
    compact_kernel<<<1, 1024>>>();

    // zero-fill content attn half (overwritten at selected columns below)
    fill_zero<<<4096, 256>>>(attn + (size_t)NTOK * NTOK);

    // attention core (flash; content heads use compacted key list)
    flash_kernel<<<dim3(32, 8), 256, FLASH_SMEM>>>();

    // attn output halves
    attn_local<<<dim3(32, 32), 256, ATTNL_SMEM>>>(attn);
    attn_content<<<dim3(NCHUNK_C, 32), 256, ATTNC_SMEM>>>(attn);

    // output projections (tf32, accumulate branches)
    proj_tf32<<<dim3(8, 32), 128>>>(p_o,              W_lproj, b_lproj, out, DDIM, 256, 0);
    proj_tf32<<<dim3(8, 32), 128>>>(p_o + NTOK * 256, W_cproj, b_cproj, out, DDIM, 256, 1);
}